// round 6
// baseline (speedup 1.0000x reference)
#include <cuda_runtime.h>
#include <cuda_bf16.h>
#include <cstdint>

#define EMB 64
#define HID 256
#define SEQ 200
#define BATCH 4096

// -------- device scratch (no allocations allowed) --------
__device__ __align__(16) __nv_bfloat16 g_Wt[256 * 128];    // folded attn W, [n][k]
__device__ __align__(16) float        g_cb[BATCH * 256];   // per-batch folded bias
__device__ __align__(16) float        g_x[BATCH * 128];    // [interest | t] per batch row

// ================= prep: fold W, gather t, compute c_b (batch-parallel) =================
// grid 512 x 256: block p handles batches [p*8, p*8+8)
__global__ __launch_bounds__(256) void prep_kernel(
    const float* __restrict__ aw1, const float* __restrict__ ab1,
    const int* __restrict__ ti, const float* __restrict__ iemb)
{
    __shared__ float ts[8][64];
    __shared__ int   tis[8];
    const int tid = threadIdx.x;
    const int b0 = blockIdx.x * 8;

    // fold Wt (first 128 blocks cover 32768 elements)
    if (blockIdx.x < 128) {
        int idx = blockIdx.x * 256 + tid;
        int n = idx >> 7, k = idx & 127;
        float v = aw1[(128 + k) * HID + n];
        if (k < 64) v += aw1[k * HID + n];
        g_Wt[n * 128 + k] = __float2bfloat16(v);
    }

    if (tid < 8) tis[tid] = ti[b0 + tid];
    __syncthreads();
    #pragma unroll
    for (int i = tid; i < 512; i += 256) {
        int row = i >> 6, e = i & 63;
        float v = iemb[(long)tis[row] * EMB + e];
        ts[row][e] = v;
        g_x[(b0 + row) * 128 + 64 + e] = v;
    }
    __syncthreads();

    // c_b[b][n] = b1[n] + sum_e t[b][e] * (W1[64+e][n] - W1[128+e][n])
    const int n = tid;
    float acc[8];
    float bias = ab1[n];
    #pragma unroll
    for (int bb = 0; bb < 8; bb++) acc[bb] = bias;
    #pragma unroll 4
    for (int e = 0; e < 64; e++) {
        float m = aw1[(64 + e) * HID + n] - aw1[(128 + e) * HID + n];
        #pragma unroll
        for (int bb = 0; bb < 8; bb++) acc[bb] = fmaf(ts[bb][e], m, acc[bb]);
    }
    #pragma unroll
    for (int bb = 0; bb < 8; bb++) g_cb[(b0 + bb) * 256 + n] = acc[bb];
}

// ================= kernel 1: gather + attention GEMM + softmax + pool =================
struct Smem1 {
    __nv_bfloat16 A[208 * 136];   // [h | h*t] bf16, padded stride 136 (68 uint32)
    float t[64];
    float cb[256];
    float w2[256];
    float logits[208];
    float red[40];
    int   idx[200];
    float part[8][64];
};

__device__ __forceinline__ void mma16816(float& c0, float& c1, float& c2, float& c3,
                                         uint32_t a0, uint32_t a1, uint32_t a2, uint32_t a3,
                                         uint32_t b0, uint32_t b1) {
    asm volatile(
        "mma.sync.aligned.m16n8k16.row.col.f32.bf16.bf16.f32 "
        "{%0,%1,%2,%3}, {%4,%5,%6,%7}, {%8,%9}, {%0,%1,%2,%3};\n"
        : "+f"(c0), "+f"(c1), "+f"(c2), "+f"(c3)
        : "r"(a0), "r"(a1), "r"(a2), "r"(a3), "r"(b0), "r"(b1));
}

__global__ __launch_bounds__(256, 2) void din_main(
    const int* __restrict__ uh,
    const float* __restrict__ uemb,
    const float* __restrict__ aw2)
{
    extern __shared__ char smraw[];
    Smem1& sm = *reinterpret_cast<Smem1*>(smraw);
    const int tid = threadIdx.x;
    const int b = blockIdx.x;
    uint32_t* Au = reinterpret_cast<uint32_t*>(sm.A);
    const int warp = tid >> 5, lane = tid & 31;
    const int lr = lane >> 2, lc = lane & 3;

    // ---- stage indices, t, cb, w2; zero pads ----
    if (tid < 200) sm.idx[tid] = uh[b * SEQ + tid];
    if (tid >= 192) sm.t[tid - 192] = g_x[b * 128 + 64 + (tid - 192)];
    sm.cb[tid] = g_cb[b * 256 + tid];
    sm.w2[tid] = aw2[tid];
    if (tid < 208) sm.logits[tid] = 0.f;
    for (int i = tid; i < 8 * 68; i += 256) Au[200 * 68 + i] = 0u;  // pad rows 200..207
    __syncthreads();

    // ---- gather h: front-batch 13 independent LDG.128, then convert+store ----
    {
        const float4* ue4 = reinterpret_cast<const float4*>(uemb);
        float4 v[13];
        int row[13], q[13];
        #pragma unroll
        for (int it = 0; it < 13; it++) {
            int i = tid + it * 256;
            row[it] = i >> 4; q[it] = i & 15;
            if (i < 3200) v[it] = ue4[(long)sm.idx[row[it]] * 16 + q[it]];
        }
        #pragma unroll
        for (int it = 0; it < 13; it++) {
            int i = tid + it * 256;
            if (i < 3200) {
                float4 vv = v[it];
                int qq = q[it];
                float t0 = sm.t[qq * 4 + 0], t1 = sm.t[qq * 4 + 1];
                float t2 = sm.t[qq * 4 + 2], t3 = sm.t[qq * 4 + 3];
                __nv_bfloat162 p0 = __floats2bfloat162_rn(vv.x, vv.y);
                __nv_bfloat162 p1 = __floats2bfloat162_rn(vv.z, vv.w);
                __nv_bfloat162 q0 = __floats2bfloat162_rn(vv.x * t0, vv.y * t1);
                __nv_bfloat162 q1 = __floats2bfloat162_rn(vv.z * t2, vv.w * t3);
                int base = row[it] * 68 + qq * 2;
                uint2 P; P.x = *reinterpret_cast<uint32_t*>(&p0); P.y = *reinterpret_cast<uint32_t*>(&p1);
                uint2 Q; Q.x = *reinterpret_cast<uint32_t*>(&q0); Q.y = *reinterpret_cast<uint32_t*>(&q1);
                *reinterpret_cast<uint2*>(Au + base) = P;
                *reinterpret_cast<uint2*>(Au + base + 32) = Q;
            }
        }
    }

    // ---- B fragments: this warp's 4 n-tiles, straight from L2 into regs ----
    uint32_t Breg[4][8][2];
    {
        const uint32_t* Wg = reinterpret_cast<const uint32_t*>(g_Wt);
        #pragma unroll
        for (int nt = 0; nt < 4; nt++) {
            int nb = (warp * 4 + nt) * 8 + lr;
            #pragma unroll
            for (int ks = 0; ks < 8; ks++) {
                Breg[nt][ks][0] = Wg[nb * 64 + ks * 8 + lc];
                Breg[nt][ks][1] = Wg[nb * 64 + ks * 8 + lc + 4];
            }
        }
    }
    __syncthreads();

    // ---- per-warp epilogue constants ----
    float cbv[4][2], w2v[4][2];
    #pragma unroll
    for (int nt = 0; nt < 4; nt++) {
        int n0 = (warp * 4 + nt) * 8 + lc * 2;
        cbv[nt][0] = sm.cb[n0];     cbv[nt][1] = sm.cb[n0 + 1];
        w2v[nt][0] = sm.w2[n0];     w2v[nt][1] = sm.w2[n0 + 1];
    }

    // per-lane ldmatrix base: row r0 + (lane&15), k-half select via (lane&16)
    const uint32_t abase = (uint32_t)__cvta_generic_to_shared(Au);
    const uint32_t rowsel = (lane & 15);
    const uint32_t khalf  = (lane & 16) ? 16u : 0u;

    // ---- GEMM: every warp sweeps all 13 slabs on its 4 n-tiles ----
    #pragma unroll 1
    for (int slab = 0; slab < 13; slab++) {
        int r0 = slab * 16 + lr;
        uint32_t lmbase = abase + (slab * 16 + rowsel) * 272 + khalf;
        uint32_t a[8][4];
        #pragma unroll
        for (int ks = 0; ks < 8; ks++) {
            asm volatile(
                "ldmatrix.sync.aligned.m8n8.x4.shared.b16 {%0,%1,%2,%3}, [%4];\n"
                : "=r"(a[ks][0]), "=r"(a[ks][1]), "=r"(a[ks][2]), "=r"(a[ks][3])
                : "r"(lmbase + ks * 32));
        }
        float c[4][4];
        #pragma unroll
        for (int nt = 0; nt < 4; nt++)
            c[nt][0] = c[nt][1] = c[nt][2] = c[nt][3] = 0.f;
        #pragma unroll
        for (int ks = 0; ks < 8; ks++) {
            #pragma unroll
            for (int nt = 0; nt < 4; nt++)
                mma16816(c[nt][0], c[nt][1], c[nt][2], c[nt][3],
                         a[ks][0], a[ks][1], a[ks][2], a[ks][3],
                         Breg[nt][ks][0], Breg[nt][ks][1]);
        }
        float lp0 = 0.f, lp1 = 0.f;
        #pragma unroll
        for (int nt = 0; nt < 4; nt++) {
            lp0 += fmaxf(c[nt][0] + cbv[nt][0], 0.f) * w2v[nt][0]
                 + fmaxf(c[nt][1] + cbv[nt][1], 0.f) * w2v[nt][1];
            lp1 += fmaxf(c[nt][2] + cbv[nt][0], 0.f) * w2v[nt][0]
                 + fmaxf(c[nt][3] + cbv[nt][1], 0.f) * w2v[nt][1];
        }
        lp0 += __shfl_xor_sync(0xffffffffu, lp0, 1);
        lp0 += __shfl_xor_sync(0xffffffffu, lp0, 2);
        lp1 += __shfl_xor_sync(0xffffffffu, lp1, 1);
        lp1 += __shfl_xor_sync(0xffffffffu, lp1, 2);
        if (lc == 0) {
            atomicAdd(&sm.logits[r0], lp0);
            atomicAdd(&sm.logits[r0 + 8], lp1);
        }
    }
    __syncthreads();

    // ---- softmax over 200 logits ----
    {
        float v = (tid < SEQ) ? sm.logits[tid] : -1e30f;
        float m = v;
        #pragma unroll
        for (int o = 16; o > 0; o >>= 1) m = fmaxf(m, __shfl_xor_sync(0xffffffffu, m, o));
        if (lane == 0) sm.red[warp] = m;
        __syncthreads();
        if (tid == 0) {
            float mm = sm.red[0];
            #pragma unroll
            for (int w = 1; w < 8; w++) mm = fmaxf(mm, sm.red[w]);
            sm.red[8] = mm;
        }
        __syncthreads();
        float mm = sm.red[8];
        float ev = (tid < SEQ) ? __expf(v - mm) : 0.f;
        float s = ev;
        #pragma unroll
        for (int o = 16; o > 0; o >>= 1) s += __shfl_xor_sync(0xffffffffu, s, o);
        if (lane == 0) sm.red[16 + warp] = s;
        __syncthreads();
        if (tid == 0) {
            float ss = 0.f;
            #pragma unroll
            for (int w = 0; w < 8; w++) ss += sm.red[16 + w];
            sm.red[9] = 1.f / ss;
        }
        __syncthreads();
        if (tid < SEQ) sm.logits[tid] = ev * sm.red[9];
    }
    __syncthreads();

    // ---- weighted pooling straight from the bf16 A tile ----
    {
        int e2 = tid & 31, chunk = tid >> 5;       // warp = one 25-row chunk
        float acc0 = 0.f, acc1 = 0.f;
        int s0 = chunk * 25;
        #pragma unroll 5
        for (int s = s0; s < s0 + 25; s++) {
            float w = sm.logits[s];
            uint32_t u = Au[s * 68 + e2];
            __nv_bfloat162 h2 = *reinterpret_cast<__nv_bfloat162*>(&u);
            acc0 = fmaf(w, __bfloat162float(h2.x), acc0);
            acc1 = fmaf(w, __bfloat162float(h2.y), acc1);
        }
        sm.part[chunk][e2 * 2]     = acc0;
        sm.part[chunk][e2 * 2 + 1] = acc1;
    }
    __syncthreads();
    if (tid < 64) {
        float v = 0.f;
        #pragma unroll
        for (int c8 = 0; c8 < 8; c8++) v += sm.part[c8][tid];
        g_x[b * 128 + tid] = v;
    }
}

// ================= kernel 2: prediction head =================
struct Smem2 {
    float w1[128 * 256];
    float b1[256];
    float w2[256];
    float xs[8 * 4 * 128];
};

__global__ __launch_bounds__(256, 1) void din_mlp(
    const float* __restrict__ mw1, const float* __restrict__ mb1,
    const float* __restrict__ mw2, const float* __restrict__ mb2,
    float* __restrict__ out)
{
    extern __shared__ char smraw[];
    Smem2& sm = *reinterpret_cast<Smem2*>(smraw);
    const int tid = threadIdx.x;

    for (int i = tid; i < 128 * 256; i += 256) sm.w1[i] = mw1[i];
    sm.b1[tid] = mb1[tid];
    sm.w2[tid] = mw2[tid];
    __syncthreads();

    const int warp = tid >> 5, lane = tid & 31;
    const int row0 = blockIdx.x * 32 + warp * 4;

    float4* xs4 = reinterpret_cast<float4*>(sm.xs + warp * 512);
    const float4* gx4 = reinterpret_cast<const float4*>(g_x);
    #pragma unroll
    for (int r = 0; r < 4; r++) xs4[r * 32 + lane] = gx4[(long)(row0 + r) * 32 + lane];
    __syncwarp();

    float d[4][8];
    #pragma unroll
    for (int r = 0; r < 4; r++)
        #pragma unroll
        for (int u = 0; u < 8; u++) d[r][u] = sm.b1[u * 32 + lane];

    const float* xw = sm.xs + warp * 512;
    for (int k = 0; k < 128; k++) {
        float w[8];
        #pragma unroll
        for (int u = 0; u < 8; u++) w[u] = sm.w1[k * 256 + u * 32 + lane];
        #pragma unroll
        for (int r = 0; r < 4; r++) {
            float xk = xw[r * 128 + k];
            #pragma unroll
            for (int u = 0; u < 8; u++) d[r][u] = fmaf(xk, w[u], d[r][u]);
        }
    }

    float b2v = mb2[0];
    float acc[4];
    #pragma unroll
    for (int r = 0; r < 4; r++) {
        float a = 0.f;
        #pragma unroll
        for (int u = 0; u < 8; u++) a += fmaxf(d[r][u], 0.f) * sm.w2[u * 32 + lane];
        #pragma unroll
        for (int o = 16; o > 0; o >>= 1) a += __shfl_xor_sync(0xffffffffu, a, o);
        acc[r] = a;
    }
    if (lane < 4) {
        float z = acc[lane] + b2v;
        out[row0 + lane] = 1.f / (1.f + __expf(-z));
    }
}

// ================= launch =================
extern "C" void kernel_launch(void* const* d_in, const int* in_sizes, int n_in,
                              void* d_out, int out_size) {
    const int*   uh   = (const int*)d_in[0];
    const int*   ti   = (const int*)d_in[1];
    const float* uemb = (const float*)d_in[2];
    const float* iemb = (const float*)d_in[3];
    const float* aw1  = (const float*)d_in[4];
    const float* ab1  = (const float*)d_in[5];
    const float* aw2  = (const float*)d_in[6];
    // d_in[7] attn_b2: softmax-invariant, unused
    const float* mw1  = (const float*)d_in[8];
    const float* mb1  = (const float*)d_in[9];
    const float* mw2  = (const float*)d_in[10];
    const float* mb2  = (const float*)d_in[11];
    float* out = (float*)d_out;

    cudaFuncSetAttribute(din_main, cudaFuncAttributeMaxDynamicSharedMemorySize, (int)sizeof(Smem1));
    cudaFuncSetAttribute(din_mlp,  cudaFuncAttributeMaxDynamicSharedMemorySize, (int)sizeof(Smem2));

    prep_kernel<<<512, 256>>>(aw1, ab1, ti, iemb);
    din_main<<<BATCH, 256, sizeof(Smem1)>>>(uh, uemb, aw2);
    din_mlp<<<128, 256, sizeof(Smem2)>>>(mw1, mb1, mw2, mb2, out);
}

// round 8
// speedup vs baseline: 1.1342x; 1.1342x over previous
#include <cuda_runtime.h>
#include <cuda_bf16.h>
#include <cstdint>

#define EMB 64
#define HID 256
#define SEQ 200
#define BATCH 4096

// -------- device scratch (no allocations allowed) --------
__device__ __align__(16) __nv_bfloat16 g_W0t[256 * 64];   // W1[0:64]+W1[128:192], [n][k] bf16
__device__ __align__(16) __nv_bfloat16 g_W1t[256 * 64];   // W1[192:256], [n][k] bf16
__device__ __align__(16) float g_cb[BATCH * 256];         // per-batch folded bias
__device__ __align__(16) float g_x[BATCH * 128];          // [interest | t] per batch row

// ================= prep: pack W0t/W1t, compute c_b, stage t =================
// grid 128 x 256: block p handles batches [p*32, p*32+32) and one W slice
__global__ __launch_bounds__(256) void prep_kernel(
    const float* __restrict__ aw1, const float* __restrict__ ab1,
    const int* __restrict__ ti, const float* __restrict__ iemb)
{
    __shared__ float ts[32][64];
    __shared__ int   tis[32];
    const int tid = threadIdx.x;
    const int b0 = blockIdx.x * 32;

    // pack W0t/W1t: 128 blocks x 256 threads = 32768 = 2 x (256n x 64k)
    {
        int idx = blockIdx.x * 256 + tid;
        int n = idx >> 7, k = idx & 127;
        if (k < 64) {
            float v = aw1[k * HID + n] + aw1[(128 + k) * HID + n];
            g_W0t[n * 64 + k] = __float2bfloat16(v);
        } else {
            g_W1t[n * 64 + (k - 64)] = __float2bfloat16(aw1[(128 + k) * HID + n]);
        }
    }

    if (tid < 32) tis[tid] = ti[b0 + tid];
    __syncthreads();
    for (int i = tid; i < 2048; i += 256) {
        int row = i >> 6, e = i & 63;
        float v = iemb[(long)tis[row] * EMB + e];
        ts[row][e] = v;
        g_x[(b0 + row) * 128 + 64 + e] = v;
    }
    __syncthreads();

    // c_b[b][n] = b1[n] + sum_e t[b][e] * (W1[64+e][n] - W1[128+e][n])
    const int n = tid;
    float acc[32];
    float bias = ab1[n];
    #pragma unroll
    for (int bb = 0; bb < 32; bb++) acc[bb] = bias;
    #pragma unroll 2
    for (int e = 0; e < 64; e++) {
        float m = aw1[(64 + e) * HID + n] - aw1[(128 + e) * HID + n];
        #pragma unroll
        for (int bb = 0; bb < 32; bb++) acc[bb] = fmaf(ts[bb][e], m, acc[bb]);
    }
    #pragma unroll
    for (int bb = 0; bb < 32; bb++) g_cb[(b0 + bb) * 256 + n] = acc[bb];
}

// ================= kernel 1: gather + rank-64 GEMM + softmax + pool =================
struct Smem1 {
    __nv_bfloat16 A[208 * 72];    // h bf16, padded stride 72 (36 uint32 / 144 B)
    float t[64];
    float cb[256];
    float w2[256];
    float logits[208];
    float red[40];
    int   idx[200];
    float part[8][64];
};

__device__ __forceinline__ void mma16816(float& c0, float& c1, float& c2, float& c3,
                                         uint32_t a0, uint32_t a1, uint32_t a2, uint32_t a3,
                                         uint32_t b0, uint32_t b1) {
    asm volatile(
        "mma.sync.aligned.m16n8k16.row.col.f32.bf16.bf16.f32 "
        "{%0,%1,%2,%3}, {%4,%5,%6,%7}, {%8,%9}, {%0,%1,%2,%3};\n"
        : "+f"(c0), "+f"(c1), "+f"(c2), "+f"(c3)
        : "r"(a0), "r"(a1), "r"(a2), "r"(a3), "r"(b0), "r"(b1));
}

__device__ __forceinline__ uint32_t fold_pair(uint32_t u0, uint32_t u1, float tk0, float tk1) {
    __nv_bfloat162 w0 = *reinterpret_cast<__nv_bfloat162*>(&u0);
    __nv_bfloat162 w1 = *reinterpret_cast<__nv_bfloat162*>(&u1);
    float r0 = fmaf(tk0, __bfloat162float(w1.x), __bfloat162float(w0.x));
    float r1 = fmaf(tk1, __bfloat162float(w1.y), __bfloat162float(w0.y));
    __nv_bfloat162 r = __floats2bfloat162_rn(r0, r1);
    return *reinterpret_cast<uint32_t*>(&r);
}

__global__ __launch_bounds__(256, 2) void din_main(
    const int* __restrict__ uh,
    const float* __restrict__ uemb,
    const float* __restrict__ aw2)
{
    extern __shared__ char smraw[];
    Smem1& sm = *reinterpret_cast<Smem1*>(smraw);
    const int tid = threadIdx.x;
    const int b = blockIdx.x;
    uint32_t* Au = reinterpret_cast<uint32_t*>(sm.A);
    const int warp = tid >> 5, lane = tid & 31;
    const int lr = lane >> 2, lc = lane & 3;

    // ---- stage indices, t, cb, w2; zero pads ----
    if (tid < 200) sm.idx[tid] = uh[b * SEQ + tid];
    if (tid >= 192) sm.t[tid - 192] = g_x[b * 128 + 64 + (tid - 192)];
    sm.cb[tid] = g_cb[b * 256 + tid];
    sm.w2[tid] = aw2[tid];
    if (tid < 208) sm.logits[tid] = 0.f;
    for (int i = tid; i < 8 * 36; i += 256) Au[200 * 36 + i] = 0u;  // pad rows 200..207
    __syncthreads();

    // ---- gather h: front-batch 13 independent LDG.128, then convert+store ----
    {
        const float4* ue4 = reinterpret_cast<const float4*>(uemb);
        float4 v[13];
        #pragma unroll
        for (int it = 0; it < 13; it++) {
            int i = tid + it * 256;
            if (i < 3200) v[it] = ue4[(long)sm.idx[i >> 4] * 16 + (i & 15)];
        }
        #pragma unroll
        for (int it = 0; it < 13; it++) {
            int i = tid + it * 256;
            if (i < 3200) {
                int row = i >> 4, q = i & 15;
                float4 vv = v[it];
                __nv_bfloat162 p0 = __floats2bfloat162_rn(vv.x, vv.y);
                __nv_bfloat162 p1 = __floats2bfloat162_rn(vv.z, vv.w);
                uint2 P;
                P.x = *reinterpret_cast<uint32_t*>(&p0);
                P.y = *reinterpret_cast<uint32_t*>(&p1);
                *reinterpret_cast<uint2*>(Au + row * 36 + q * 2) = P;
            }
        }
    }

    // ---- build B_b fragments in registers: B_b = W0t + t ∘ W1t (per n-row) ----
    uint32_t Breg[4][4][2];
    {
        const uint32_t* W0u = reinterpret_cast<const uint32_t*>(g_W0t);
        const uint32_t* W1u = reinterpret_cast<const uint32_t*>(g_W1t);
        float tk[4][2][2];   // t at k = ks*16 + lc*2 (+1), and +8
        #pragma unroll
        for (int ks = 0; ks < 4; ks++) {
            int k0 = ks * 16 + lc * 2;
            tk[ks][0][0] = sm.t[k0];     tk[ks][0][1] = sm.t[k0 + 1];
            tk[ks][1][0] = sm.t[k0 + 8]; tk[ks][1][1] = sm.t[k0 + 9];
        }
        #pragma unroll
        for (int nt = 0; nt < 4; nt++) {
            int nb = (warp * 4 + nt) * 8 + lr;
            #pragma unroll
            for (int ks = 0; ks < 4; ks++) {
                uint32_t a0 = W0u[nb * 32 + ks * 8 + lc];
                uint32_t a1 = W1u[nb * 32 + ks * 8 + lc];
                uint32_t b0 = W0u[nb * 32 + ks * 8 + lc + 4];
                uint32_t b1 = W1u[nb * 32 + ks * 8 + lc + 4];
                Breg[nt][ks][0] = fold_pair(a0, a1, tk[ks][0][0], tk[ks][0][1]);
                Breg[nt][ks][1] = fold_pair(b0, b1, tk[ks][1][0], tk[ks][1][1]);
            }
        }
    }
    __syncthreads();

    // ---- per-warp epilogue constants ----
    float cbv[4][2], w2v[4][2];
    #pragma unroll
    for (int nt = 0; nt < 4; nt++) {
        int n0 = (warp * 4 + nt) * 8 + lc * 2;
        cbv[nt][0] = sm.cb[n0];     cbv[nt][1] = sm.cb[n0 + 1];
        w2v[nt][0] = sm.w2[n0];     w2v[nt][1] = sm.w2[n0 + 1];
    }

    // per-lane ldmatrix base: rows (lane&15), k-half via (lane&16)
    const uint32_t abase = (uint32_t)__cvta_generic_to_shared(Au);
    const uint32_t rowsel = (lane & 15);
    const uint32_t khalf  = (lane & 16) ? 16u : 0u;

    // ---- GEMM: every warp sweeps all 13 slabs on its 4 n-tiles (K=64: 4 k-steps) ----
    #pragma unroll 1
    for (int slab = 0; slab < 13; slab++) {
        int r0 = slab * 16 + lr;
        uint32_t lmbase = abase + (slab * 16 + rowsel) * 144 + khalf;
        uint32_t a[4][4];
        #pragma unroll
        for (int ks = 0; ks < 4; ks++) {
            asm volatile(
                "ldmatrix.sync.aligned.m8n8.x4.shared.b16 {%0,%1,%2,%3}, [%4];\n"
                : "=r"(a[ks][0]), "=r"(a[ks][1]), "=r"(a[ks][2]), "=r"(a[ks][3])
                : "r"(lmbase + ks * 32));
        }
        float c[4][4];
        #pragma unroll
        for (int nt = 0; nt < 4; nt++)
            c[nt][0] = c[nt][1] = c[nt][2] = c[nt][3] = 0.f;
        #pragma unroll
        for (int ks = 0; ks < 4; ks++) {
            #pragma unroll
            for (int nt = 0; nt < 4; nt++)
                mma16816(c[nt][0], c[nt][1], c[nt][2], c[nt][3],
                         a[ks][0], a[ks][1], a[ks][2], a[ks][3],
                         Breg[nt][ks][0], Breg[nt][ks][1]);
        }
        float lp0 = 0.f, lp1 = 0.f;
        #pragma unroll
        for (int nt = 0; nt < 4; nt++) {
            lp0 += fmaxf(c[nt][0] + cbv[nt][0], 0.f) * w2v[nt][0]
                 + fmaxf(c[nt][1] + cbv[nt][1], 0.f) * w2v[nt][1];
            lp1 += fmaxf(c[nt][2] + cbv[nt][0], 0.f) * w2v[nt][0]
                 + fmaxf(c[nt][3] + cbv[nt][1], 0.f) * w2v[nt][1];
        }
        lp0 += __shfl_xor_sync(0xffffffffu, lp0, 1);
        lp0 += __shfl_xor_sync(0xffffffffu, lp0, 2);
        lp1 += __shfl_xor_sync(0xffffffffu, lp1, 1);
        lp1 += __shfl_xor_sync(0xffffffffu, lp1, 2);
        if (lc == 0) {
            atomicAdd(&sm.logits[r0], lp0);
            atomicAdd(&sm.logits[r0 + 8], lp1);
        }
    }
    __syncthreads();

    // ---- softmax over 200 logits ----
    {
        float v = (tid < SEQ) ? sm.logits[tid] : -1e30f;
        float m = v;
        #pragma unroll
        for (int o = 16; o > 0; o >>= 1) m = fmaxf(m, __shfl_xor_sync(0xffffffffu, m, o));
        if (lane == 0) sm.red[warp] = m;
        __syncthreads();
        if (tid == 0) {
            float mm = sm.red[0];
            #pragma unroll
            for (int w = 1; w < 8; w++) mm = fmaxf(mm, sm.red[w]);
            sm.red[8] = mm;
        }
        __syncthreads();
        float mm = sm.red[8];
        float ev = (tid < SEQ) ? __expf(v - mm) : 0.f;
        float s = ev;
        #pragma unroll
        for (int o = 16; o > 0; o >>= 1) s += __shfl_xor_sync(0xffffffffu, s, o);
        if (lane == 0) sm.red[16 + warp] = s;
        __syncthreads();
        if (tid == 0) {
            float ss = 0.f;
            #pragma unroll
            for (int w = 0; w < 8; w++) ss += sm.red[16 + w];
            sm.red[9] = 1.f / ss;
        }
        __syncthreads();
        if (tid < SEQ) sm.logits[tid] = ev * sm.red[9];
    }
    __syncthreads();

    // ---- weighted pooling from bf16 A tile ----
    {
        int e2 = lane, chunk = warp;          // warp = one 25-row chunk
        float acc0 = 0.f, acc1 = 0.f;
        int s0 = chunk * 25;
        #pragma unroll 5
        for (int s = s0; s < s0 + 25; s++) {
            float w = sm.logits[s];
            uint32_t u = Au[s * 36 + e2];
            __nv_bfloat162 h2 = *reinterpret_cast<__nv_bfloat162*>(&u);
            acc0 = fmaf(w, __bfloat162float(h2.x), acc0);
            acc1 = fmaf(w, __bfloat162float(h2.y), acc1);
        }
        sm.part[chunk][e2 * 2]     = acc0;
        sm.part[chunk][e2 * 2 + 1] = acc1;
    }
    __syncthreads();
    if (tid < 64) {
        float v = 0.f;
        #pragma unroll
        for (int c8 = 0; c8 < 8; c8++) v += sm.part[c8][tid];
        g_x[b * 128 + tid] = v;
    }
}

// ================= kernel 2: prediction head =================
struct Smem2 {
    float w1[128 * 256];
    float b1[256];
    float w2[256];
    float xs[8 * 4 * 128];
};

__global__ __launch_bounds__(256, 1) void din_mlp(
    const float* __restrict__ mw1, const float* __restrict__ mb1,
    const float* __restrict__ mw2, const float* __restrict__ mb2,
    float* __restrict__ out)
{
    extern __shared__ char smraw[];
    Smem2& sm = *reinterpret_cast<Smem2*>(smraw);
    const int tid = threadIdx.x;

    for (int i = tid; i < 128 * 256; i += 256) sm.w1[i] = mw1[i];
    sm.b1[tid] = mb1[tid];
    sm.w2[tid] = mw2[tid];
    __syncthreads();

    const int warp = tid >> 5, lane = tid & 31;
    const int row0 = blockIdx.x * 32 + warp * 4;

    float4* xs4 = reinterpret_cast<float4*>(sm.xs + warp * 512);
    const float4* gx4 = reinterpret_cast<const float4*>(g_x);
    #pragma unroll
    for (int r = 0; r < 4; r++) xs4[r * 32 + lane] = gx4[(long)(row0 + r) * 32 + lane];
    __syncwarp();

    float d[4][8];
    #pragma unroll
    for (int r = 0; r < 4; r++)
        #pragma unroll
        for (int u = 0; u < 8; u++) d[r][u] = sm.b1[u * 32 + lane];

    const float* xw = sm.xs + warp * 512;
    for (int k = 0; k < 128; k++) {
        float w[8];
        #pragma unroll
        for (int u = 0; u < 8; u++) w[u] = sm.w1[k * 256 + u * 32 + lane];
        #pragma unroll
        for (int r = 0; r < 4; r++) {
            float xk = xw[r * 128 + k];
            #pragma unroll
            for (int u = 0; u < 8; u++) d[r][u] = fmaf(xk, w[u], d[r][u]);
        }
    }

    float b2v = mb2[0];
    float acc[4];
    #pragma unroll
    for (int r = 0; r < 4; r++) {
        float a = 0.f;
        #pragma unroll
        for (int u = 0; u < 8; u++) a += fmaxf(d[r][u], 0.f) * sm.w2[u * 32 + lane];
        #pragma unroll
        for (int o = 16; o > 0; o >>= 1) a += __shfl_xor_sync(0xffffffffu, a, o);
        acc[r] = a;
    }
    if (lane < 4) {
        float z = acc[lane] + b2v;
        out[row0 + lane] = 1.f / (1.f + __expf(-z));
    }
}

// ================= launch =================
extern "C" void kernel_launch(void* const* d_in, const int* in_sizes, int n_in,
                              void* d_out, int out_size) {
    const int*   uh   = (const int*)d_in[0];
    const int*   ti   = (const int*)d_in[1];
    const float* uemb = (const float*)d_in[2];
    const float* iemb = (const float*)d_in[3];
    const float* aw1  = (const float*)d_in[4];
    const float* ab1  = (const float*)d_in[5];
    const float* aw2  = (const float*)d_in[6];
    // d_in[7] attn_b2: softmax-invariant, unused
    const float* mw1  = (const float*)d_in[8];
    const float* mb1  = (const float*)d_in[9];
    const float* mw2  = (const float*)d_in[10];
    const float* mb2  = (const float*)d_in[11];
    float* out = (float*)d_out;

    cudaFuncSetAttribute(din_main, cudaFuncAttributeMaxDynamicSharedMemorySize, (int)sizeof(Smem1));
    cudaFuncSetAttribute(din_mlp,  cudaFuncAttributeMaxDynamicSharedMemorySize, (int)sizeof(Smem2));

    prep_kernel<<<128, 256>>>(aw1, ab1, ti, iemb);
    din_main<<<BATCH, 256, sizeof(Smem1)>>>(uh, uemb, aw2);
    din_mlp<<<128, 256, sizeof(Smem2)>>>(mw1, mb1, mw2, mb2, out);
}

// round 9
// speedup vs baseline: 1.3264x; 1.1695x over previous
#include <cuda_runtime.h>
#include <cuda_bf16.h>
#include <cuda_fp8.h>
#include <cstdint>

#define EMB 64
#define HID 256
#define SEQ 200
#define BATCH 4096

// -------- device scratch (no allocations allowed) --------
__device__ __align__(16) __nv_bfloat16 g_W0t[256 * 64];   // W1[0:64]+W1[128:192], [n][k] bf16
__device__ __align__(16) __nv_bfloat16 g_W1t[256 * 64];   // W1[192:256], [n][k] bf16
__device__ __align__(16) float g_cb[BATCH * 256];         // per-batch folded bias
__device__ __align__(16) float g_x[BATCH * 128];          // [interest | t] per batch row

#define FP8_SCALE 64.0f
#define INV_SCALE (1.0f / 4096.0f)

// ================= prep: pack W0t/W1t, compute c_b, stage t =================
// grid 256 x 256: block p handles batches [p*16, p*16+16) and W slice p (128 elems)
__global__ __launch_bounds__(256) void prep_kernel(
    const float* __restrict__ aw1, const float* __restrict__ ab1,
    const int* __restrict__ ti, const float* __restrict__ iemb)
{
    __shared__ float ts[16][64];
    __shared__ int   tis[16];
    const int tid = threadIdx.x;
    const int b0 = blockIdx.x * 16;

    // pack W0t/W1t: 256 blocks x 128 elems = 32768 = 2 x (256n x 64k)
    if (tid < 128) {
        int idx = blockIdx.x * 128 + tid;
        int n = idx >> 6, k2 = idx & 63;
        // first 16384 -> W0t, rest -> W1t, interleave by n
        if (n < 256) {
            float v = aw1[k2 * HID + n] + aw1[(128 + k2) * HID + n];
            g_W0t[n * 64 + k2] = __float2bfloat16(v);
        } else {
            g_W1t[(n - 256) * 64 + k2] = __float2bfloat16(aw1[(192 + k2) * HID + (n - 256)]);
        }
    }

    if (tid < 16) tis[tid] = ti[b0 + tid];
    __syncthreads();
    for (int i = tid; i < 1024; i += 256) {
        int row = i >> 6, e = i & 63;
        float v = iemb[(long)tis[row] * EMB + e];
        ts[row][e] = v;
        g_x[(b0 + row) * 128 + 64 + e] = v;
    }
    __syncthreads();

    // c_b[b][n] = b1[n] + sum_e t[b][e] * (W1[64+e][n] - W1[128+e][n])
    const int n = tid;
    float acc[16];
    float bias = ab1[n];
    #pragma unroll
    for (int bb = 0; bb < 16; bb++) acc[bb] = bias;
    #pragma unroll 4
    for (int e = 0; e < 64; e++) {
        float m = aw1[(64 + e) * HID + n] - aw1[(128 + e) * HID + n];
        #pragma unroll
        for (int bb = 0; bb < 16; bb++) acc[bb] = fmaf(ts[bb][e], m, acc[bb]);
    }
    #pragma unroll
    for (int bb = 0; bb < 16; bb++) g_cb[(b0 + bb) * 256 + n] = acc[bb];
}

// ================= kernel 1: gather + fp8 rank-64 GEMM + softmax + pool =================
struct Smem1 {
    uint8_t A[208 * 80];              // h e4m3 x64, row stride 80 B (64 data + 16 pad)
    __nv_bfloat16 pool[208 * 64];     // h bf16 for pooling, stride 64 (128 B rows)
    float t[64];
    float cb[256];
    float w2[256];
    float logits[208];
    float red[40];
    int   idx[200];
    float part[8][64];
};

__device__ __forceinline__ void mma_fp8(float& c0, float& c1, float& c2, float& c3,
                                        uint32_t a0, uint32_t a1, uint32_t a2, uint32_t a3,
                                        uint32_t b0, uint32_t b1) {
    asm volatile(
        "mma.sync.aligned.m16n8k32.row.col.f32.e4m3.e4m3.f32 "
        "{%0,%1,%2,%3}, {%4,%5,%6,%7}, {%8,%9}, {%0,%1,%2,%3};\n"
        : "+f"(c0), "+f"(c1), "+f"(c2), "+f"(c3)
        : "r"(a0), "r"(a1), "r"(a2), "r"(a3), "r"(b0), "r"(b1));
}

__device__ __forceinline__ uint32_t pack_e4m3_4(float a, float b, float c, float d) {
    __nv_fp8x2_storage_t lo = __nv_cvt_float2_to_fp8x2(make_float2(a, b), __NV_SATFINITE, __NV_E4M3);
    __nv_fp8x2_storage_t hi = __nv_cvt_float2_to_fp8x2(make_float2(c, d), __NV_SATFINITE, __NV_E4M3);
    return (uint32_t)lo | ((uint32_t)hi << 16);
}

__global__ __launch_bounds__(256, 4) void din_main(
    const int* __restrict__ uh,
    const float* __restrict__ uemb,
    const float* __restrict__ aw2)
{
    extern __shared__ char smraw[];
    Smem1& sm = *reinterpret_cast<Smem1*>(smraw);
    const int tid = threadIdx.x;
    const int b = blockIdx.x;
    const int warp = tid >> 5, lane = tid & 31;
    const int lr = lane >> 2, lc = lane & 3;
    uint32_t* PoolU = reinterpret_cast<uint32_t*>(sm.pool);

    // ---- stage indices, t, cb, w2; zero pads ----
    if (tid < 200) sm.idx[tid] = uh[b * SEQ + tid];
    if (tid >= 192) sm.t[tid - 192] = g_x[b * 128 + 64 + (tid - 192)];
    sm.cb[tid] = g_cb[b * 256 + tid];
    sm.w2[tid] = aw2[tid];
    if (tid < 208) sm.logits[tid] = 0.f;
    if (tid < 160) reinterpret_cast<uint32_t*>(sm.A + 200 * 80)[tid] = 0u;  // pad rows 200..207
    __syncthreads();

    // ---- gather h: two front-batched waves (7 + 6), convert to e4m3 + bf16 ----
    {
        const float4* ue4 = reinterpret_cast<const float4*>(uemb);
        #pragma unroll
        for (int half = 0; half < 2; half++) {
            const int cnt = half ? 6 : 7;
            const int base0 = half ? 7 * 256 : 0;
            float4 v[7];
            #pragma unroll
            for (int it = 0; it < 7; it++) {
                if (it < cnt) {
                    int i = base0 + tid + it * 256;
                    if (i < 3200) v[it] = ue4[(long)sm.idx[i >> 4] * 16 + (i & 15)];
                }
            }
            #pragma unroll
            for (int it = 0; it < 7; it++) {
                if (it < cnt) {
                    int i = base0 + tid + it * 256;
                    if (i < 3200) {
                        int row = i >> 4, q = i & 15;
                        float4 vv = v[it];
                        // fp8 A (x64)
                        *reinterpret_cast<uint32_t*>(sm.A + row * 80 + q * 4) =
                            pack_e4m3_4(vv.x * FP8_SCALE, vv.y * FP8_SCALE,
                                        vv.z * FP8_SCALE, vv.w * FP8_SCALE);
                        // bf16 pool copy
                        __nv_bfloat162 p0 = __floats2bfloat162_rn(vv.x, vv.y);
                        __nv_bfloat162 p1 = __floats2bfloat162_rn(vv.z, vv.w);
                        uint2 P;
                        P.x = *reinterpret_cast<uint32_t*>(&p0);
                        P.y = *reinterpret_cast<uint32_t*>(&p1);
                        *reinterpret_cast<uint2*>(PoolU + row * 32 + q * 2) = P;
                    }
                }
            }
        }
    }

    // ---- build fp8 B fragments in regs: B_b = (W0t + t ∘ W1t) * 64 ----
    uint32_t Breg[4][2][2];   // [ntile][ks2][b0/b1]
    {
        const uint32_t* W0u = reinterpret_cast<const uint32_t*>(g_W0t);
        const uint32_t* W1u = reinterpret_cast<const uint32_t*>(g_W1t);
        #pragma unroll
        for (int nt = 0; nt < 4; nt++) {
            int nb = (warp * 4 + nt) * 8 + lr;
            #pragma unroll
            for (int ks2 = 0; ks2 < 2; ks2++) {
                int ub = nb * 32 + ks2 * 16 + lc * 2;   // uint32 index, k = ks2*32 + lc*4
                #pragma unroll
                for (int part = 0; part < 2; part++) {  // b0 (k+0..3), b1 (k+16..19)
                    int u0i = ub + part * 8;
                    uint32_t w0a = W0u[u0i],     w0b = W0u[u0i + 1];
                    uint32_t w1a = W1u[u0i],     w1b = W1u[u0i + 1];
                    int k0 = ks2 * 32 + part * 16 + lc * 4;
                    __nv_bfloat162 x0 = *reinterpret_cast<__nv_bfloat162*>(&w0a);
                    __nv_bfloat162 x1 = *reinterpret_cast<__nv_bfloat162*>(&w0b);
                    __nv_bfloat162 y0 = *reinterpret_cast<__nv_bfloat162*>(&w1a);
                    __nv_bfloat162 y1 = *reinterpret_cast<__nv_bfloat162*>(&w1b);
                    float f0 = fmaf(sm.t[k0 + 0], __bfloat162float(y0.x), __bfloat162float(x0.x)) * FP8_SCALE;
                    float f1 = fmaf(sm.t[k0 + 1], __bfloat162float(y0.y), __bfloat162float(x0.y)) * FP8_SCALE;
                    float f2 = fmaf(sm.t[k0 + 2], __bfloat162float(y1.x), __bfloat162float(x1.x)) * FP8_SCALE;
                    float f3 = fmaf(sm.t[k0 + 3], __bfloat162float(y1.y), __bfloat162float(x1.y)) * FP8_SCALE;
                    Breg[nt][ks2][part] = pack_e4m3_4(f0, f1, f2, f3);
                }
            }
        }
    }
    __syncthreads();

    // per-lane ldmatrix base: row (lane&15), 16-byte half via (lane&16)
    const uint32_t abase = (uint32_t)__cvta_generic_to_shared(sm.A);
    const uint32_t rowsel = (lane & 15);
    const uint32_t khalf  = (lane & 16) ? 16u : 0u;

    // ---- GEMM: every warp sweeps all 13 slabs on its 4 n-tiles (2 fp8 k-steps) ----
    #pragma unroll 1
    for (int slab = 0; slab < 13; slab++) {
        int r0 = slab * 16 + lr;
        uint32_t lmbase = abase + (slab * 16 + rowsel) * 80 + khalf;
        uint32_t a[2][4];
        #pragma unroll
        for (int ks2 = 0; ks2 < 2; ks2++) {
            asm volatile(
                "ldmatrix.sync.aligned.m8n8.x4.shared.b16 {%0,%1,%2,%3}, [%4];\n"
                : "=r"(a[ks2][0]), "=r"(a[ks2][1]), "=r"(a[ks2][2]), "=r"(a[ks2][3])
                : "r"(lmbase + ks2 * 32));
        }
        float c[4][4];
        #pragma unroll
        for (int nt = 0; nt < 4; nt++)
            c[nt][0] = c[nt][1] = c[nt][2] = c[nt][3] = 0.f;
        #pragma unroll
        for (int ks2 = 0; ks2 < 2; ks2++) {
            #pragma unroll
            for (int nt = 0; nt < 4; nt++)
                mma_fp8(c[nt][0], c[nt][1], c[nt][2], c[nt][3],
                        a[ks2][0], a[ks2][1], a[ks2][2], a[ks2][3],
                        Breg[nt][ks2][0], Breg[nt][ks2][1]);
        }
        float lp0 = 0.f, lp1 = 0.f;
        #pragma unroll
        for (int nt = 0; nt < 4; nt++) {
            int n0 = (warp * 4 + nt) * 8 + lc * 2;
            float cb0 = sm.cb[n0], cb1 = sm.cb[n0 + 1];
            float w20 = sm.w2[n0], w21 = sm.w2[n0 + 1];
            lp0 += fmaxf(fmaf(c[nt][0], INV_SCALE, cb0), 0.f) * w20
                 + fmaxf(fmaf(c[nt][1], INV_SCALE, cb1), 0.f) * w21;
            lp1 += fmaxf(fmaf(c[nt][2], INV_SCALE, cb0), 0.f) * w20
                 + fmaxf(fmaf(c[nt][3], INV_SCALE, cb1), 0.f) * w21;
        }
        lp0 += __shfl_xor_sync(0xffffffffu, lp0, 1);
        lp0 += __shfl_xor_sync(0xffffffffu, lp0, 2);
        lp1 += __shfl_xor_sync(0xffffffffu, lp1, 1);
        lp1 += __shfl_xor_sync(0xffffffffu, lp1, 2);
        if (lc == 0) {
            atomicAdd(&sm.logits[r0], lp0);
            atomicAdd(&sm.logits[r0 + 8], lp1);
        }
    }
    __syncthreads();

    // ---- softmax over 200 logits ----
    {
        float v = (tid < SEQ) ? sm.logits[tid] : -1e30f;
        float m = v;
        #pragma unroll
        for (int o = 16; o > 0; o >>= 1) m = fmaxf(m, __shfl_xor_sync(0xffffffffu, m, o));
        if (lane == 0) sm.red[warp] = m;
        __syncthreads();
        if (tid == 0) {
            float mm = sm.red[0];
            #pragma unroll
            for (int w = 1; w < 8; w++) mm = fmaxf(mm, sm.red[w]);
            sm.red[8] = mm;
        }
        __syncthreads();
        float mm = sm.red[8];
        float ev = (tid < SEQ) ? __expf(v - mm) : 0.f;
        float s = ev;
        #pragma unroll
        for (int o = 16; o > 0; o >>= 1) s += __shfl_xor_sync(0xffffffffu, s, o);
        if (lane == 0) sm.red[16 + warp] = s;
        __syncthreads();
        if (tid == 0) {
            float ss = 0.f;
            #pragma unroll
            for (int w = 0; w < 8; w++) ss += sm.red[16 + w];
            sm.red[9] = 1.f / ss;
        }
        __syncthreads();
        if (tid < SEQ) sm.logits[tid] = ev * sm.red[9];
    }
    __syncthreads();

    // ---- weighted pooling from bf16 pool tile ----
    {
        int e2 = lane, chunk = warp;          // warp = one 25-row chunk
        float acc0 = 0.f, acc1 = 0.f;
        int s0 = chunk * 25;
        #pragma unroll 5
        for (int s = s0; s < s0 + 25; s++) {
            float w = sm.logits[s];
            uint32_t u = PoolU[s * 32 + e2];
            __nv_bfloat162 h2 = *reinterpret_cast<__nv_bfloat162*>(&u);
            acc0 = fmaf(w, __bfloat162float(h2.x), acc0);
            acc1 = fmaf(w, __bfloat162float(h2.y), acc1);
        }
        sm.part[chunk][e2 * 2]     = acc0;
        sm.part[chunk][e2 * 2 + 1] = acc1;
    }
    __syncthreads();
    if (tid < 64) {
        float v = 0.f;
        #pragma unroll
        for (int c8 = 0; c8 < 8; c8++) v += sm.part[c8][tid];
        g_x[b * 128 + tid] = v;
    }
}

// ================= kernel 2: prediction head =================
struct Smem2 {
    float w1[128 * 256];
    float b1[256];
    float w2[256];
    float xs[8 * 4 * 128];
};

__global__ __launch_bounds__(256, 1) void din_mlp(
    const float* __restrict__ mw1, const float* __restrict__ mb1,
    const float* __restrict__ mw2, const float* __restrict__ mb2,
    float* __restrict__ out)
{
    extern __shared__ char smraw[];
    Smem2& sm = *reinterpret_cast<Smem2*>(smraw);
    const int tid = threadIdx.x;

    for (int i = tid; i < 128 * 256; i += 256) sm.w1[i] = mw1[i];
    sm.b1[tid] = mb1[tid];
    sm.w2[tid] = mw2[tid];
    __syncthreads();

    const int warp = tid >> 5, lane = tid & 31;
    const int row0 = blockIdx.x * 32 + warp * 4;

    float4* xs4 = reinterpret_cast<float4*>(sm.xs + warp * 512);
    const float4* gx4 = reinterpret_cast<const float4*>(g_x);
    #pragma unroll
    for (int r = 0; r < 4; r++) xs4[r * 32 + lane] = gx4[(long)(row0 + r) * 32 + lane];
    __syncwarp();

    float d[4][8];
    #pragma unroll
    for (int r = 0; r < 4; r++)
        #pragma unroll
        for (int u = 0; u < 8; u++) d[r][u] = sm.b1[u * 32 + lane];

    const float* xw = sm.xs + warp * 512;
    for (int k = 0; k < 128; k++) {
        float w[8];
        #pragma unroll
        for (int u = 0; u < 8; u++) w[u] = sm.w1[k * 256 + u * 32 + lane];
        #pragma unroll
        for (int r = 0; r < 4; r++) {
            float xk = xw[r * 128 + k];
            #pragma unroll
            for (int u = 0; u < 8; u++) d[r][u] = fmaf(xk, w[u], d[r][u]);
        }
    }

    float b2v = mb2[0];
    float acc[4];
    #pragma unroll
    for (int r = 0; r < 4; r++) {
        float a = 0.f;
        #pragma unroll
        for (int u = 0; u < 8; u++) a += fmaxf(d[r][u], 0.f) * sm.w2[u * 32 + lane];
        #pragma unroll
        for (int o = 16; o > 0; o >>= 1) a += __shfl_xor_sync(0xffffffffu, a, o);
        acc[r] = a;
    }
    if (lane < 4) {
        float z = acc[lane] + b2v;
        out[row0 + lane] = 1.f / (1.f + __expf(-z));
    }
}

// ================= launch =================
extern "C" void kernel_launch(void* const* d_in, const int* in_sizes, int n_in,
                              void* d_out, int out_size) {
    const int*   uh   = (const int*)d_in[0];
    const int*   ti   = (const int*)d_in[1];
    const float* uemb = (const float*)d_in[2];
    const float* iemb = (const float*)d_in[3];
    const float* aw1  = (const float*)d_in[4];
    const float* ab1  = (const float*)d_in[5];
    const float* aw2  = (const float*)d_in[6];
    // d_in[7] attn_b2: softmax-invariant, unused
    const float* mw1  = (const float*)d_in[8];
    const float* mb1  = (const float*)d_in[9];
    const float* mw2  = (const float*)d_in[10];
    const float* mb2  = (const float*)d_in[11];
    float* out = (float*)d_out;

    cudaFuncSetAttribute(din_main, cudaFuncAttributeMaxDynamicSharedMemorySize, (int)sizeof(Smem1));
    cudaFuncSetAttribute(din_mlp,  cudaFuncAttributeMaxDynamicSharedMemorySize, (int)sizeof(Smem2));

    prep_kernel<<<256, 256>>>(aw1, ab1, ti, iemb);
    din_main<<<BATCH, 256, sizeof(Smem1)>>>(uh, uemb, aw2);
    din_mlp<<<128, 256, sizeof(Smem2)>>>(mw1, mb1, mw2, mb2, out);
}

// round 10
// speedup vs baseline: 1.3537x; 1.0206x over previous
#include <cuda_runtime.h>
#include <cuda_bf16.h>
#include <cuda_fp8.h>
#include <cstdint>

#define EMB 64
#define HID 256
#define SEQ 200
#define BATCH 4096
#define VOCAB 100000

// -------- device scratch (no allocations allowed) --------
__device__ __align__(16) __nv_bfloat16 g_emb[VOCAB * EMB]; // bf16 copy of user_emb (12.8 MB)
__device__ __align__(16) __nv_bfloat16 g_W0t[256 * 64];    // W1[0:64]+W1[128:192], [n][k] bf16
__device__ __align__(16) __nv_bfloat16 g_W1t[256 * 64];    // W1[192:256], [n][k] bf16
__device__ __align__(16) float g_cb[BATCH * 256];          // per-batch folded bias
__device__ __align__(16) float g_x[BATCH * 128];           // [interest | t] per batch row

#define FP8_SCALE 64.0f
#define INV_SCALE (1.0f / 4096.0f)

// ================= prep: convert table to bf16; pack W; compute c_b =================
// grid 2048 x 256: all blocks convert a table slice; blocks [0,256) also do c_b + W pack
__global__ __launch_bounds__(256) void prep_kernel(
    const float* __restrict__ uemb,
    const float* __restrict__ aw1, const float* __restrict__ ab1,
    const int* __restrict__ ti, const float* __restrict__ iemb)
{
    __shared__ float ts[16][64];
    __shared__ int   tis[16];
    const int tid = threadIdx.x;

    // ---- table fp32 -> bf16 (1.6M float4 groups, grid-stride) ----
    {
        const float4* src = reinterpret_cast<const float4*>(uemb);
        uint2* dst = reinterpret_cast<uint2*>(g_emb);
        for (int j = blockIdx.x * 256 + tid; j < (VOCAB * EMB / 4); j += 2048 * 256) {
            float4 vv = src[j];
            __nv_bfloat162 p0 = __floats2bfloat162_rn(vv.x, vv.y);
            __nv_bfloat162 p1 = __floats2bfloat162_rn(vv.z, vv.w);
            uint2 P;
            P.x = *reinterpret_cast<uint32_t*>(&p0);
            P.y = *reinterpret_cast<uint32_t*>(&p1);
            dst[j] = P;
        }
    }

    if (blockIdx.x >= 256) return;
    const int b0 = blockIdx.x * 16;

    // pack W0t/W1t: 256 blocks x 128 elems = 32768 = 2 x (256n x 64k)
    if (tid < 128) {
        int idx = blockIdx.x * 128 + tid;
        int n = idx >> 6, k2 = idx & 63;
        if (n < 256) {
            float v = aw1[k2 * HID + n] + aw1[(128 + k2) * HID + n];
            g_W0t[n * 64 + k2] = __float2bfloat16(v);
        } else {
            g_W1t[(n - 256) * 64 + k2] = __float2bfloat16(aw1[(192 + k2) * HID + (n - 256)]);
        }
    }

    if (tid < 16) tis[tid] = ti[b0 + tid];
    __syncthreads();
    for (int i = tid; i < 1024; i += 256) {
        int row = i >> 6, e = i & 63;
        float v = iemb[(long)tis[row] * EMB + e];
        ts[row][e] = v;
        g_x[(b0 + row) * 128 + 64 + e] = v;
    }
    __syncthreads();

    // c_b[b][n] = b1[n] + sum_e t[b][e] * (W1[64+e][n] - W1[128+e][n])
    const int n = tid;
    float acc[16];
    float bias = ab1[n];
    #pragma unroll
    for (int bb = 0; bb < 16; bb++) acc[bb] = bias;
    #pragma unroll 4
    for (int e = 0; e < 64; e++) {
        float m = aw1[(64 + e) * HID + n] - aw1[(128 + e) * HID + n];
        #pragma unroll
        for (int bb = 0; bb < 16; bb++) acc[bb] = fmaf(ts[bb][e], m, acc[bb]);
    }
    #pragma unroll
    for (int bb = 0; bb < 16; bb++) g_cb[(b0 + bb) * 256 + n] = acc[bb];
}

// ================= kernel 1: gather + fp8 rank-64 GEMM + softmax + pool =================
struct Smem1 {
    uint8_t A[208 * 80];              // h e4m3 x64, row stride 80 B
    __nv_bfloat16 pool[208 * 64];     // h bf16 for pooling, stride 64 (128 B rows)
    float t[64];
    float cb[256];
    float w2[256];
    float logits[208];
    float red[40];
    int   idx[200];
    float part[8][64];
};

__device__ __forceinline__ void mma_fp8(float& c0, float& c1, float& c2, float& c3,
                                        uint32_t a0, uint32_t a1, uint32_t a2, uint32_t a3,
                                        uint32_t b0, uint32_t b1) {
    asm volatile(
        "mma.sync.aligned.m16n8k32.row.col.f32.e4m3.e4m3.f32 "
        "{%0,%1,%2,%3}, {%4,%5,%6,%7}, {%8,%9}, {%0,%1,%2,%3};\n"
        : "+f"(c0), "+f"(c1), "+f"(c2), "+f"(c3)
        : "r"(a0), "r"(a1), "r"(a2), "r"(a3), "r"(b0), "r"(b1));
}

__device__ __forceinline__ uint32_t pack_e4m3_4(float a, float b, float c, float d) {
    __nv_fp8x2_storage_t lo = __nv_cvt_float2_to_fp8x2(make_float2(a, b), __NV_SATFINITE, __NV_E4M3);
    __nv_fp8x2_storage_t hi = __nv_cvt_float2_to_fp8x2(make_float2(c, d), __NV_SATFINITE, __NV_E4M3);
    return (uint32_t)lo | ((uint32_t)hi << 16);
}

__global__ __launch_bounds__(256, 4) void din_main(
    const int* __restrict__ uh,
    const float* __restrict__ aw2)
{
    extern __shared__ char smraw[];
    Smem1& sm = *reinterpret_cast<Smem1*>(smraw);
    const int tid = threadIdx.x;
    const int b = blockIdx.x;
    const int warp = tid >> 5, lane = tid & 31;
    const int lr = lane >> 2, lc = lane & 3;
    uint32_t* PoolU = reinterpret_cast<uint32_t*>(sm.pool);

    // ---- stage indices, t, cb, w2; zero pads ----
    if (tid < 200) sm.idx[tid] = uh[b * SEQ + tid];
    if (tid >= 192) sm.t[tid - 192] = g_x[b * 128 + 64 + (tid - 192)];
    sm.cb[tid] = g_cb[b * 256 + tid];
    sm.w2[tid] = aw2[tid];
    if (tid < 208) sm.logits[tid] = 0.f;
    if (tid < 160) reinterpret_cast<uint32_t*>(sm.A + 200 * 80)[tid] = 0u;  // pad rows 200..207
    __syncthreads();

    // ---- gather h (bf16 table): 1600 uint4 groups, front-batched ----
    {
        const uint4* ue = reinterpret_cast<const uint4*>(g_emb);   // 8 uint4 per row
        uint4 v[7];
        #pragma unroll
        for (int it = 0; it < 7; it++) {
            int i = tid + it * 256;
            if (i < 1600) v[it] = ue[(long)sm.idx[i >> 3] * 8 + (i & 7)];
        }
        #pragma unroll
        for (int it = 0; it < 7; it++) {
            int i = tid + it * 256;
            if (i < 1600) {
                int row = i >> 3, q = i & 7;          // q: 8-element (16B) chunk
                uint4 vv = v[it];
                // bf16 pool copy (raw)
                *reinterpret_cast<uint4*>(PoolU + row * 32 + q * 4) = vv;
                // fp8 A: unpack 8 bf16, scale, pack
                float2 f0 = __bfloat1622float2(*reinterpret_cast<__nv_bfloat162*>(&vv.x));
                float2 f1 = __bfloat1622float2(*reinterpret_cast<__nv_bfloat162*>(&vv.y));
                float2 f2 = __bfloat1622float2(*reinterpret_cast<__nv_bfloat162*>(&vv.z));
                float2 f3 = __bfloat1622float2(*reinterpret_cast<__nv_bfloat162*>(&vv.w));
                uint2 E;
                E.x = pack_e4m3_4(f0.x * FP8_SCALE, f0.y * FP8_SCALE,
                                  f1.x * FP8_SCALE, f1.y * FP8_SCALE);
                E.y = pack_e4m3_4(f2.x * FP8_SCALE, f2.y * FP8_SCALE,
                                  f3.x * FP8_SCALE, f3.y * FP8_SCALE);
                *reinterpret_cast<uint2*>(sm.A + row * 80 + q * 8) = E;
            }
        }
    }

    // ---- build fp8 B fragments in regs: B_b = (W0t + t ∘ W1t) * 64 ----
    uint32_t Breg[4][2][2];   // [ntile][ks2][b0/b1]
    {
        const uint32_t* W0u = reinterpret_cast<const uint32_t*>(g_W0t);
        const uint32_t* W1u = reinterpret_cast<const uint32_t*>(g_W1t);
        #pragma unroll
        for (int nt = 0; nt < 4; nt++) {
            int nb = (warp * 4 + nt) * 8 + lr;
            #pragma unroll
            for (int ks2 = 0; ks2 < 2; ks2++) {
                int ub = nb * 32 + ks2 * 16 + lc * 2;
                #pragma unroll
                for (int part = 0; part < 2; part++) {
                    int u0i = ub + part * 8;
                    uint32_t w0a = W0u[u0i],     w0b = W0u[u0i + 1];
                    uint32_t w1a = W1u[u0i],     w1b = W1u[u0i + 1];
                    int k0 = ks2 * 32 + part * 16 + lc * 4;
                    __nv_bfloat162 x0 = *reinterpret_cast<__nv_bfloat162*>(&w0a);
                    __nv_bfloat162 x1 = *reinterpret_cast<__nv_bfloat162*>(&w0b);
                    __nv_bfloat162 y0 = *reinterpret_cast<__nv_bfloat162*>(&w1a);
                    __nv_bfloat162 y1 = *reinterpret_cast<__nv_bfloat162*>(&w1b);
                    float f0 = fmaf(sm.t[k0 + 0], __bfloat162float(y0.x), __bfloat162float(x0.x)) * FP8_SCALE;
                    float f1 = fmaf(sm.t[k0 + 1], __bfloat162float(y0.y), __bfloat162float(x0.y)) * FP8_SCALE;
                    float f2 = fmaf(sm.t[k0 + 2], __bfloat162float(y1.x), __bfloat162float(x1.x)) * FP8_SCALE;
                    float f3 = fmaf(sm.t[k0 + 3], __bfloat162float(y1.y), __bfloat162float(x1.y)) * FP8_SCALE;
                    Breg[nt][ks2][part] = pack_e4m3_4(f0, f1, f2, f3);
                }
            }
        }
    }
    __syncthreads();

    // per-lane ldmatrix base: row (lane&15), 16-byte half via (lane&16)
    const uint32_t abase = (uint32_t)__cvta_generic_to_shared(sm.A);
    const uint32_t rowsel = (lane & 15);
    const uint32_t khalf  = (lane & 16) ? 16u : 0u;

    // ---- GEMM: every warp sweeps all 13 slabs on its 4 n-tiles (2 fp8 k-steps) ----
    #pragma unroll 1
    for (int slab = 0; slab < 13; slab++) {
        int r0 = slab * 16 + lr;
        uint32_t lmbase = abase + (slab * 16 + rowsel) * 80 + khalf;
        uint32_t a[2][4];
        #pragma unroll
        for (int ks2 = 0; ks2 < 2; ks2++) {
            asm volatile(
                "ldmatrix.sync.aligned.m8n8.x4.shared.b16 {%0,%1,%2,%3}, [%4];\n"
                : "=r"(a[ks2][0]), "=r"(a[ks2][1]), "=r"(a[ks2][2]), "=r"(a[ks2][3])
                : "r"(lmbase + ks2 * 32));
        }
        float c[4][4];
        #pragma unroll
        for (int nt = 0; nt < 4; nt++)
            c[nt][0] = c[nt][1] = c[nt][2] = c[nt][3] = 0.f;
        #pragma unroll
        for (int ks2 = 0; ks2 < 2; ks2++) {
            #pragma unroll
            for (int nt = 0; nt < 4; nt++)
                mma_fp8(c[nt][0], c[nt][1], c[nt][2], c[nt][3],
                        a[ks2][0], a[ks2][1], a[ks2][2], a[ks2][3],
                        Breg[nt][ks2][0], Breg[nt][ks2][1]);
        }
        float lp0 = 0.f, lp1 = 0.f;
        #pragma unroll
        for (int nt = 0; nt < 4; nt++) {
            int n0 = (warp * 4 + nt) * 8 + lc * 2;
            float cb0 = sm.cb[n0], cb1 = sm.cb[n0 + 1];
            float w20 = sm.w2[n0], w21 = sm.w2[n0 + 1];
            lp0 += fmaxf(fmaf(c[nt][0], INV_SCALE, cb0), 0.f) * w20
                 + fmaxf(fmaf(c[nt][1], INV_SCALE, cb1), 0.f) * w21;
            lp1 += fmaxf(fmaf(c[nt][2], INV_SCALE, cb0), 0.f) * w20
                 + fmaxf(fmaf(c[nt][3], INV_SCALE, cb1), 0.f) * w21;
        }
        lp0 += __shfl_xor_sync(0xffffffffu, lp0, 1);
        lp0 += __shfl_xor_sync(0xffffffffu, lp0, 2);
        lp1 += __shfl_xor_sync(0xffffffffu, lp1, 1);
        lp1 += __shfl_xor_sync(0xffffffffu, lp1, 2);
        if (lc == 0) {
            atomicAdd(&sm.logits[r0], lp0);
            atomicAdd(&sm.logits[r0 + 8], lp1);
        }
    }
    __syncthreads();

    // ---- softmax over 200 logits (no max-sub: |logit| << 1 by construction) ----
    {
        float ev = (tid < SEQ) ? __expf(sm.logits[tid]) : 0.f;
        float s = ev;
        #pragma unroll
        for (int o = 16; o > 0; o >>= 1) s += __shfl_xor_sync(0xffffffffu, s, o);
        if (lane == 0) sm.red[warp] = s;
        __syncthreads();
        if (tid == 0) {
            float ss = 0.f;
            #pragma unroll
            for (int w = 0; w < 8; w++) ss += sm.red[w];
            sm.red[9] = 1.f / ss;
        }
        __syncthreads();
        if (tid < SEQ) sm.logits[tid] = ev * sm.red[9];
    }
    __syncthreads();

    // ---- weighted pooling from bf16 pool tile ----
    {
        int e2 = lane, chunk = warp;          // warp = one 25-row chunk
        float acc0 = 0.f, acc1 = 0.f;
        int s0 = chunk * 25;
        #pragma unroll 5
        for (int s = s0; s < s0 + 25; s++) {
            float w = sm.logits[s];
            uint32_t u = PoolU[s * 32 + e2];
            __nv_bfloat162 h2 = *reinterpret_cast<__nv_bfloat162*>(&u);
            acc0 = fmaf(w, __bfloat162float(h2.x), acc0);
            acc1 = fmaf(w, __bfloat162float(h2.y), acc1);
        }
        sm.part[chunk][e2 * 2]     = acc0;
        sm.part[chunk][e2 * 2 + 1] = acc1;
    }
    __syncthreads();
    if (tid < 64) {
        float v = 0.f;
        #pragma unroll
        for (int c8 = 0; c8 < 8; c8++) v += sm.part[c8][tid];
        g_x[b * 128 + tid] = v;
    }
}

// ================= kernel 2: prediction head =================
struct Smem2 {
    float w1[128 * 256];
    float b1[256];
    float w2[256];
    float xs[8 * 4 * 128];
};

__global__ __launch_bounds__(256, 1) void din_mlp(
    const float* __restrict__ mw1, const float* __restrict__ mb1,
    const float* __restrict__ mw2, const float* __restrict__ mb2,
    float* __restrict__ out)
{
    extern __shared__ char smraw[];
    Smem2& sm = *reinterpret_cast<Smem2*>(smraw);
    const int tid = threadIdx.x;

    for (int i = tid; i < 128 * 256; i += 256) sm.w1[i] = mw1[i];
    sm.b1[tid] = mb1[tid];
    sm.w2[tid] = mw2[tid];
    __syncthreads();

    const int warp = tid >> 5, lane = tid & 31;
    const int row0 = blockIdx.x * 32 + warp * 4;

    float4* xs4 = reinterpret_cast<float4*>(sm.xs + warp * 512);
    const float4* gx4 = reinterpret_cast<const float4*>(g_x);
    #pragma unroll
    for (int r = 0; r < 4; r++) xs4[r * 32 + lane] = gx4[(long)(row0 + r) * 32 + lane];
    __syncwarp();

    float d[4][8];
    #pragma unroll
    for (int r = 0; r < 4; r++)
        #pragma unroll
        for (int u = 0; u < 8; u++) d[r][u] = sm.b1[u * 32 + lane];

    const float* xw = sm.xs + warp * 512;
    for (int k = 0; k < 128; k++) {
        float w[8];
        #pragma unroll
        for (int u = 0; u < 8; u++) w[u] = sm.w1[k * 256 + u * 32 + lane];
        #pragma unroll
        for (int r = 0; r < 4; r++) {
            float xk = xw[r * 128 + k];
            #pragma unroll
            for (int u = 0; u < 8; u++) d[r][u] = fmaf(xk, w[u], d[r][u]);
        }
    }

    float b2v = mb2[0];
    float acc[4];
    #pragma unroll
    for (int r = 0; r < 4; r++) {
        float a = 0.f;
        #pragma unroll
        for (int u = 0; u < 8; u++) a += fmaxf(d[r][u], 0.f) * sm.w2[u * 32 + lane];
        #pragma unroll
        for (int o = 16; o > 0; o >>= 1) a += __shfl_xor_sync(0xffffffffu, a, o);
        acc[r] = a;
    }
    if (lane < 4) {
        float z = acc[lane] + b2v;
        out[row0 + lane] = 1.f / (1.f + __expf(-z));
    }
}

// ================= launch =================
extern "C" void kernel_launch(void* const* d_in, const int* in_sizes, int n_in,
                              void* d_out, int out_size) {
    const int*   uh   = (const int*)d_in[0];
    const int*   ti   = (const int*)d_in[1];
    const float* uemb = (const float*)d_in[2];
    const float* iemb = (const float*)d_in[3];
    const float* aw1  = (const float*)d_in[4];
    const float* ab1  = (const float*)d_in[5];
    const float* aw2  = (const float*)d_in[6];
    // d_in[7] attn_b2: softmax-invariant, unused
    const float* mw1  = (const float*)d_in[8];
    const float* mb1  = (const float*)d_in[9];
    const float* mw2  = (const float*)d_in[10];
    const float* mb2  = (const float*)d_in[11];
    float* out = (float*)d_out;

    cudaFuncSetAttribute(din_main, cudaFuncAttributeMaxDynamicSharedMemorySize, (int)sizeof(Smem1));
    cudaFuncSetAttribute(din_mlp,  cudaFuncAttributeMaxDynamicSharedMemorySize, (int)sizeof(Smem2));

    prep_kernel<<<2048, 256>>>(uemb, aw1, ab1, ti, iemb);
    din_main<<<BATCH, 256, sizeof(Smem1)>>>(uh, aw2);
    din_mlp<<<128, 256, sizeof(Smem2)>>>(mw1, mb1, mw2, mb2, out);
}

// round 11
// speedup vs baseline: 1.7749x; 1.3111x over previous
#include <cuda_runtime.h>
#include <cuda_bf16.h>
#include <cuda_fp16.h>
#include <cuda_fp8.h>
#include <cstdint>

#define EMB 64
#define HID 256
#define SEQ 200
#define BATCH 4096
#define VOCAB 100000

// -------- device scratch (no allocations allowed) --------
__device__ __align__(16) __nv_bfloat16 g_emb[VOCAB * EMB]; // bf16 copy of user_emb (12.8 MB)
__device__ __align__(16) uint32_t g_W0f[256 * 32];         // W1[0:64]+W1[128:192], fragment-ordered bf16x2
__device__ __align__(16) uint32_t g_W1f[256 * 32];         // W1[192:256], fragment-ordered bf16x2
__device__ __align__(16) float g_cb[BATCH * 256];          // per-batch folded bias
__device__ __align__(16) float g_x[BATCH * 128];           // [interest | t] per batch row

#define FP8_SCALE 64.0f
#define INV_SCALE (1.0f / 4096.0f)

// ================= prep A: stream-convert embedding table to bf16 =================
__global__ __launch_bounds__(256) void prep_conv(const float* __restrict__ uemb) {
    const float4* src = reinterpret_cast<const float4*>(uemb);
    uint2* dst = reinterpret_cast<uint2*>(g_emb);
    for (int j = blockIdx.x * 256 + threadIdx.x; j < (VOCAB * EMB / 4); j += 2048 * 256) {
        float4 vv = src[j];
        __nv_bfloat162 p0 = __floats2bfloat162_rn(vv.x, vv.y);
        __nv_bfloat162 p1 = __floats2bfloat162_rn(vv.z, vv.w);
        uint2 P;
        P.x = *reinterpret_cast<uint32_t*>(&p0);
        P.y = *reinterpret_cast<uint32_t*>(&p1);
        dst[j] = P;
    }
}

// ================= prep B: pack W fragments; compute c_b; stage t =================
// grid 256 x 256: block p handles batches [p*16, p*16+16) and a W slice
__global__ __launch_bounds__(256) void prep_misc(
    const float* __restrict__ aw1, const float* __restrict__ ab1,
    const int* __restrict__ ti, const float* __restrict__ iemb)
{
    __shared__ float ts[16][64];
    __shared__ int   tis[16];
    const int tid = threadIdx.x;
    const int b0 = blockIdx.x * 16;

    // pack W0f/W1f in per-lane fragment order: word u (k=2u,2u+1) of n-row n goes to
    // fi = ((u>>1)&3)*8 + (u>>4)*4 + ((u>>3)&1)*2 + (u&1)
    if (tid < 128) {
        int idx = blockIdx.x * 128 + tid;         // 0..32767
        int m = idx >> 14;                         // 0: W0, 1: W1
        int r = idx & 16383;
        int n = r >> 5, u = r & 31, k = u * 2;
        float v0, v1;
        if (m == 0) {
            v0 = aw1[k * HID + n] + aw1[(128 + k) * HID + n];
            v1 = aw1[(k + 1) * HID + n] + aw1[(129 + k) * HID + n];
        } else {
            v0 = aw1[(192 + k) * HID + n];
            v1 = aw1[(193 + k) * HID + n];
        }
        __nv_bfloat162 p = __floats2bfloat162_rn(v0, v1);
        int fi = ((u >> 1) & 3) * 8 + (u >> 4) * 4 + ((u >> 3) & 1) * 2 + (u & 1);
        (m ? g_W1f : g_W0f)[n * 32 + fi] = *reinterpret_cast<uint32_t*>(&p);
    }

    if (tid < 16) tis[tid] = ti[b0 + tid];
    __syncthreads();
    for (int i = tid; i < 1024; i += 256) {
        int row = i >> 6, e = i & 63;
        float v = iemb[(long)tis[row] * EMB + e];
        ts[row][e] = v;
        g_x[(b0 + row) * 128 + 64 + e] = v;
    }
    __syncthreads();

    // c_b[b][n] = b1[n] + sum_e t[b][e] * (W1[64+e][n] - W1[128+e][n])
    const int n = tid;
    float acc[16];
    float bias = ab1[n];
    #pragma unroll
    for (int bb = 0; bb < 16; bb++) acc[bb] = bias;
    #pragma unroll 4
    for (int e = 0; e < 64; e++) {
        float m = aw1[(64 + e) * HID + n] - aw1[(128 + e) * HID + n];
        #pragma unroll
        for (int bb = 0; bb < 16; bb++) acc[bb] = fmaf(ts[bb][e], m, acc[bb]);
    }
    #pragma unroll
    for (int bb = 0; bb < 16; bb++) g_cb[(b0 + bb) * 256 + n] = acc[bb];
}

// ================= kernel 1: gather + fp8 GEMM (f16 acc) + softmax + pool =================
struct Smem1 {
    uint8_t A[208 * 80];              // h e4m3 x64, row stride 80 B
    __nv_bfloat16 pool[208 * 64];     // h bf16 for pooling (128 B rows)
    float t[64];
    float cb[256];
    float w2[256];
    float logits[208];
    float plog[8][208];               // per-warp partial logits; reused for pooling partials
    float red[16];
    int   idx[200];
};

__device__ __forceinline__ void mma_fp8_h(uint32_t& d0, uint32_t& d1,
                                          uint32_t a0, uint32_t a1, uint32_t a2, uint32_t a3,
                                          uint32_t b0, uint32_t b1) {
    asm volatile(
        "mma.sync.aligned.m16n8k32.row.col.f16.e4m3.e4m3.f16 "
        "{%0,%1}, {%2,%3,%4,%5}, {%6,%7}, {%0,%1};\n"
        : "+r"(d0), "+r"(d1)
        : "r"(a0), "r"(a1), "r"(a2), "r"(a3), "r"(b0), "r"(b1));
}

__device__ __forceinline__ uint32_t pack_e4m3_4(float a, float b, float c, float d) {
    __nv_fp8x2_storage_t lo = __nv_cvt_float2_to_fp8x2(make_float2(a, b), __NV_SATFINITE, __NV_E4M3);
    __nv_fp8x2_storage_t hi = __nv_cvt_float2_to_fp8x2(make_float2(c, d), __NV_SATFINITE, __NV_E4M3);
    return (uint32_t)lo | ((uint32_t)hi << 16);
}

__device__ __forceinline__ float2 bf2f2(uint32_t u) {
    return __bfloat1622float2(*reinterpret_cast<__nv_bfloat162*>(&u));
}

__global__ __launch_bounds__(256, 4) void din_main(
    const int* __restrict__ uh,
    const float* __restrict__ aw2)
{
    extern __shared__ char smraw[];
    Smem1& sm = *reinterpret_cast<Smem1*>(smraw);
    const int tid = threadIdx.x;
    const int b = blockIdx.x;
    const int warp = tid >> 5, lane = tid & 31;
    const int lr = lane >> 2, lc = lane & 3;
    uint32_t* PoolU = reinterpret_cast<uint32_t*>(sm.pool);

    // ---- stage indices, t, cb, w2; zero pads ----
    if (tid < 200) sm.idx[tid] = uh[b * SEQ + tid];
    if (tid >= 192) sm.t[tid - 192] = g_x[b * 128 + 64 + (tid - 192)];
    sm.cb[tid] = g_cb[b * 256 + tid];
    sm.w2[tid] = aw2[tid];
    if (tid < 160) reinterpret_cast<uint32_t*>(sm.A + 200 * 80)[tid] = 0u;  // pad rows 200..207
    __syncthreads();

    // ---- gather h (bf16 table): 1600 uint4 groups, front-batched ----
    {
        const uint4* ue = reinterpret_cast<const uint4*>(g_emb);   // 8 uint4 per row
        uint4 v[7];
        #pragma unroll
        for (int it = 0; it < 7; it++) {
            int i = tid + it * 256;
            if (i < 1600) v[it] = ue[(long)sm.idx[i >> 3] * 8 + (i & 7)];
        }
        #pragma unroll
        for (int it = 0; it < 7; it++) {
            int i = tid + it * 256;
            if (i < 1600) {
                int row = i >> 3, q = i & 7;
                uint4 vv = v[it];
                *reinterpret_cast<uint4*>(PoolU + row * 32 + q * 4) = vv;   // bf16 pool copy
                float2 f0 = bf2f2(vv.x), f1 = bf2f2(vv.y);
                float2 f2 = bf2f2(vv.z), f3 = bf2f2(vv.w);
                uint2 E;
                E.x = pack_e4m3_4(f0.x * FP8_SCALE, f0.y * FP8_SCALE,
                                  f1.x * FP8_SCALE, f1.y * FP8_SCALE);
                E.y = pack_e4m3_4(f2.x * FP8_SCALE, f2.y * FP8_SCALE,
                                  f3.x * FP8_SCALE, f3.y * FP8_SCALE);
                *reinterpret_cast<uint2*>(sm.A + row * 80 + q * 8) = E;
            }
        }
    }

    // ---- build fp8 B fragments: B_b = (W0 + t ∘ W1) * 64, fragment-ordered uint4 loads ----
    uint32_t Breg[4][2][2];   // [ntile][ks2][part]
    {
        const uint4* W0q = reinterpret_cast<const uint4*>(g_W0f);
        const uint4* W1q = reinterpret_cast<const uint4*>(g_W1f);
        #pragma unroll
        for (int nt = 0; nt < 4; nt++) {
            int nb = (warp * 4 + nt) * 8 + lr;
            int base = nb * 8 + lc * 2;
            uint4 q0a = W0q[base], q0b = W0q[base + 1];
            uint4 q1a = W1q[base], q1b = W1q[base + 1];
            #pragma unroll
            for (int half = 0; half < 4; half++) {
                uint32_t w0lo = half == 0 ? q0a.x : half == 1 ? q0a.z : half == 2 ? q0b.x : q0b.z;
                uint32_t w0hi = half == 0 ? q0a.y : half == 1 ? q0a.w : half == 2 ? q0b.y : q0b.w;
                uint32_t w1lo = half == 0 ? q1a.x : half == 1 ? q1a.z : half == 2 ? q1b.x : q1b.z;
                uint32_t w1hi = half == 0 ? q1a.y : half == 1 ? q1a.w : half == 2 ? q1b.y : q1b.w;
                int k0 = (half >> 1) * 32 + (half & 1) * 16 + lc * 4;
                float2 x0 = bf2f2(w0lo), x1 = bf2f2(w0hi);
                float2 y0 = bf2f2(w1lo), y1 = bf2f2(w1hi);
                float f0 = fmaf(sm.t[k0 + 0], y0.x, x0.x) * FP8_SCALE;
                float f1 = fmaf(sm.t[k0 + 1], y0.y, x0.y) * FP8_SCALE;
                float f2 = fmaf(sm.t[k0 + 2], y1.x, x1.x) * FP8_SCALE;
                float f3 = fmaf(sm.t[k0 + 3], y1.y, x1.y) * FP8_SCALE;
                Breg[nt][half >> 1][half & 1] = pack_e4m3_4(f0, f1, f2, f3);
            }
        }
    }
    __syncthreads();

    // ---- packed epilogue constants: cb*4096 and w2 as half2 pairs ----
    __half2 cbp[4], w2p[4];
    const __half2 z2 = __floats2half2_rn(0.f, 0.f);
    #pragma unroll
    for (int nt = 0; nt < 4; nt++) {
        int n0 = (warp * 4 + nt) * 8 + lc * 2;
        cbp[nt] = __floats2half2_rn(sm.cb[n0] * 4096.f, sm.cb[n0 + 1] * 4096.f);
        w2p[nt] = __floats2half2_rn(sm.w2[n0], sm.w2[n0 + 1]);
    }

    const uint32_t abase = (uint32_t)__cvta_generic_to_shared(sm.A);
    const uint32_t rowsel = (lane & 15);
    const uint32_t khalf  = (lane & 16) ? 16u : 0u;

    // ---- GEMM: 13 slabs x 4 n-tiles, f16 accumulators, packed epilogue ----
    #pragma unroll 1
    for (int slab = 0; slab < 13; slab++) {
        int r0 = slab * 16 + lr;
        uint32_t lmbase = abase + (slab * 16 + rowsel) * 80 + khalf;
        uint32_t a[2][4];
        #pragma unroll
        for (int ks2 = 0; ks2 < 2; ks2++) {
            asm volatile(
                "ldmatrix.sync.aligned.m8n8.x4.shared.b16 {%0,%1,%2,%3}, [%4];\n"
                : "=r"(a[ks2][0]), "=r"(a[ks2][1]), "=r"(a[ks2][2]), "=r"(a[ks2][3])
                : "r"(lmbase + ks2 * 32));
        }
        uint32_t d[4][2];
        #pragma unroll
        for (int nt = 0; nt < 4; nt++) d[nt][0] = d[nt][1] = 0u;
        #pragma unroll
        for (int ks2 = 0; ks2 < 2; ks2++) {
            #pragma unroll
            for (int nt = 0; nt < 4; nt++)
                mma_fp8_h(d[nt][0], d[nt][1],
                          a[ks2][0], a[ks2][1], a[ks2][2], a[ks2][3],
                          Breg[nt][ks2][0], Breg[nt][ks2][1]);
        }
        __half2 l0 = z2, l1 = z2;
        #pragma unroll
        for (int nt = 0; nt < 4; nt++) {
            __half2 d0 = *reinterpret_cast<__half2*>(&d[nt][0]);
            __half2 d1 = *reinterpret_cast<__half2*>(&d[nt][1]);
            l0 = __hfma2(__hmax2(__hadd2(d0, cbp[nt]), z2), w2p[nt], l0);
            l1 = __hfma2(__hmax2(__hadd2(d1, cbp[nt]), z2), w2p[nt], l1);
        }
        float lp0 = (__low2float(l0) + __high2float(l0)) * INV_SCALE;
        float lp1 = (__low2float(l1) + __high2float(l1)) * INV_SCALE;
        lp0 += __shfl_xor_sync(0xffffffffu, lp0, 1);
        lp0 += __shfl_xor_sync(0xffffffffu, lp0, 2);
        lp1 += __shfl_xor_sync(0xffffffffu, lp1, 1);
        lp1 += __shfl_xor_sync(0xffffffffu, lp1, 2);
        if (lc == 0) {
            sm.plog[warp][r0] = lp0;
            sm.plog[warp][r0 + 8] = lp1;
        }
    }
    __syncthreads();

    // ---- softmax over 200 logits (sum 8 warp-partials; no max-sub: |logit| << 1) ----
    {
        float v = 0.f;
        if (tid < SEQ) {
            #pragma unroll
            for (int w = 0; w < 8; w++) v += sm.plog[w][tid];
        }
        float ev = (tid < SEQ) ? __expf(v) : 0.f;
        float s = ev;
        #pragma unroll
        for (int o = 16; o > 0; o >>= 1) s += __shfl_xor_sync(0xffffffffu, s, o);
        if (lane == 0) sm.red[warp] = s;
        __syncthreads();
        if (tid == 0) {
            float ss = 0.f;
            #pragma unroll
            for (int w = 0; w < 8; w++) ss += sm.red[w];
            sm.red[8] = 1.f / ss;
        }
        __syncthreads();
        if (tid < SEQ) sm.logits[tid] = ev * sm.red[8];
    }
    __syncthreads();

    // ---- weighted pooling from bf16 pool tile (partials reuse plog space) ----
    float* part = &sm.plog[0][0];    // 8 chunks x 64 floats
    {
        int e2 = lane, chunk = warp;
        float acc0 = 0.f, acc1 = 0.f;
        int s0 = chunk * 25;
        #pragma unroll 5
        for (int s = s0; s < s0 + 25; s++) {
            float w = sm.logits[s];
            uint32_t u = PoolU[s * 32 + e2];
            __nv_bfloat162 h2 = *reinterpret_cast<__nv_bfloat162*>(&u);
            acc0 = fmaf(w, __bfloat162float(h2.x), acc0);
            acc1 = fmaf(w, __bfloat162float(h2.y), acc1);
        }
        part[chunk * 64 + e2 * 2]     = acc0;
        part[chunk * 64 + e2 * 2 + 1] = acc1;
    }
    __syncthreads();
    if (tid < 64) {
        float v = 0.f;
        #pragma unroll
        for (int c8 = 0; c8 < 8; c8++) v += part[c8 * 64 + tid];
        g_x[b * 128 + tid] = v;
    }
}

// ================= kernel 2: prediction head =================
struct Smem2 {
    float w1[128 * 256];
    float b1[256];
    float w2[256];
    float xs[8 * 4 * 128];
};

__global__ __launch_bounds__(256, 1) void din_mlp(
    const float* __restrict__ mw1, const float* __restrict__ mb1,
    const float* __restrict__ mw2, const float* __restrict__ mb2,
    float* __restrict__ out)
{
    extern __shared__ char smraw[];
    Smem2& sm = *reinterpret_cast<Smem2*>(smraw);
    const int tid = threadIdx.x;

    for (int i = tid; i < 128 * 256; i += 256) sm.w1[i] = mw1[i];
    sm.b1[tid] = mb1[tid];
    sm.w2[tid] = mw2[tid];
    __syncthreads();

    const int warp = tid >> 5, lane = tid & 31;
    const int row0 = blockIdx.x * 32 + warp * 4;

    float4* xs4 = reinterpret_cast<float4*>(sm.xs + warp * 512);
    const float4* gx4 = reinterpret_cast<const float4*>(g_x);
    #pragma unroll
    for (int r = 0; r < 4; r++) xs4[r * 32 + lane] = gx4[(long)(row0 + r) * 32 + lane];
    __syncwarp();

    float d[4][8];
    #pragma unroll
    for (int r = 0; r < 4; r++)
        #pragma unroll
        for (int u = 0; u < 8; u++) d[r][u] = sm.b1[u * 32 + lane];

    const float* xw = sm.xs + warp * 512;
    for (int k = 0; k < 128; k++) {
        float w[8];
        #pragma unroll
        for (int u = 0; u < 8; u++) w[u] = sm.w1[k * 256 + u * 32 + lane];
        #pragma unroll
        for (int r = 0; r < 4; r++) {
            float xk = xw[r * 128 + k];
            #pragma unroll
            for (int u = 0; u < 8; u++) d[r][u] = fmaf(xk, w[u], d[r][u]);
        }
    }

    float b2v = mb2[0];
    float acc[4];
    #pragma unroll
    for (int r = 0; r < 4; r++) {
        float a = 0.f;
        #pragma unroll
        for (int u = 0; u < 8; u++) a += fmaxf(d[r][u], 0.f) * sm.w2[u * 32 + lane];
        #pragma unroll
        for (int o = 16; o > 0; o >>= 1) a += __shfl_xor_sync(0xffffffffu, a, o);
        acc[r] = a;
    }
    if (lane < 4) {
        float z = acc[lane] + b2v;
        out[row0 + lane] = 1.f / (1.f + __expf(-z));
    }
}

// ================= launch =================
extern "C" void kernel_launch(void* const* d_in, const int* in_sizes, int n_in,
                              void* d_out, int out_size) {
    const int*   uh   = (const int*)d_in[0];
    const int*   ti   = (const int*)d_in[1];
    const float* uemb = (const float*)d_in[2];
    const float* iemb = (const float*)d_in[3];
    const float* aw1  = (const float*)d_in[4];
    const float* ab1  = (const float*)d_in[5];
    const float* aw2  = (const float*)d_in[6];
    // d_in[7] attn_b2: softmax-invariant, unused
    const float* mw1  = (const float*)d_in[8];
    const float* mb1  = (const float*)d_in[9];
    const float* mw2  = (const float*)d_in[10];
    const float* mb2  = (const float*)d_in[11];
    float* out = (float*)d_out;

    cudaFuncSetAttribute(din_main, cudaFuncAttributeMaxDynamicSharedMemorySize, (int)sizeof(Smem1));
    cudaFuncSetAttribute(din_mlp,  cudaFuncAttributeMaxDynamicSharedMemorySize, (int)sizeof(Smem2));

    prep_conv<<<2048, 256>>>(uemb);
    prep_misc<<<256, 256>>>(aw1, ab1, ti, iemb);
    din_main<<<BATCH, 256, sizeof(Smem1)>>>(uh, aw2);
    din_mlp<<<128, 256, sizeof(Smem2)>>>(mw1, mb1, mw2, mb2, out);
}

// round 12
// speedup vs baseline: 1.8089x; 1.0192x over previous
#include <cuda_runtime.h>
#include <cuda_bf16.h>
#include <cuda_fp16.h>
#include <cuda_fp8.h>
#include <cstdint>

#define EMB 64
#define HID 256
#define SEQ 200
#define BATCH 4096
#define VOCAB 100000

// -------- device scratch (no allocations allowed) --------
__device__ __align__(16) __nv_bfloat16 g_emb[VOCAB * EMB]; // bf16 copy of user_emb (12.8 MB)
__device__ __align__(16) uint32_t g_W0f[256 * 32];         // W1[0:64]+W1[128:192], fragment-ordered bf16x2
__device__ __align__(16) uint32_t g_W1f[256 * 32];         // W1[192:256], fragment-ordered bf16x2
__device__ __align__(16) float g_cb[BATCH * 256];          // per-batch folded bias
__device__ __align__(16) float g_x[BATCH * 128];           // [interest | t] per batch row

#define FP8_SCALE 64.0f
#define INV_SCALE (1.0f / 4096.0f)

// ================= prep A: stream-convert embedding table to bf16 (ILP 4) =================
__global__ __launch_bounds__(256) void prep_conv(const float* __restrict__ uemb) {
    const float4* src = reinterpret_cast<const float4*>(uemb);
    uint2* dst = reinterpret_cast<uint2*>(g_emb);
    const int gid = blockIdx.x * 256 + threadIdx.x;         // 524288 threads
    const int total = VOCAB * EMB / 4;                      // 1.6M groups
    float4 v[4];
    #pragma unroll
    for (int s = 0; s < 4; s++) {
        int j = gid + s * 524288;
        if (j < total) v[s] = src[j];
    }
    #pragma unroll
    for (int s = 0; s < 4; s++) {
        int j = gid + s * 524288;
        if (j < total) {
            float4 vv = v[s];
            __nv_bfloat162 p0 = __floats2bfloat162_rn(vv.x, vv.y);
            __nv_bfloat162 p1 = __floats2bfloat162_rn(vv.z, vv.w);
            uint2 P;
            P.x = *reinterpret_cast<uint32_t*>(&p0);
            P.y = *reinterpret_cast<uint32_t*>(&p1);
            dst[j] = P;
        }
    }
}

// ================= prep B: pack W fragments; compute c_b; stage t =================
// grid 256 x 256: block p handles batches [p*16, p*16+16) and a W slice
__global__ __launch_bounds__(256) void prep_misc(
    const float* __restrict__ aw1, const float* __restrict__ ab1,
    const int* __restrict__ ti, const float* __restrict__ iemb)
{
    __shared__ float ts[16][64];
    __shared__ int   tis[16];
    const int tid = threadIdx.x;
    const int b0 = blockIdx.x * 16;

    // pack W0f/W1f in per-lane fragment order: word u (k=2u,2u+1) of n-row n goes to
    // fi = ((u>>1)&3)*8 + (u>>4)*4 + ((u>>3)&1)*2 + (u&1)
    if (tid < 128) {
        int idx = blockIdx.x * 128 + tid;         // 0..32767
        int m = idx >> 14;                         // 0: W0, 1: W1
        int r = idx & 16383;
        int n = r >> 5, u = r & 31, k = u * 2;
        float v0, v1;
        if (m == 0) {
            v0 = aw1[k * HID + n] + aw1[(128 + k) * HID + n];
            v1 = aw1[(k + 1) * HID + n] + aw1[(129 + k) * HID + n];
        } else {
            v0 = aw1[(192 + k) * HID + n];
            v1 = aw1[(193 + k) * HID + n];
        }
        __nv_bfloat162 p = __floats2bfloat162_rn(v0, v1);
        int fi = ((u >> 1) & 3) * 8 + (u >> 4) * 4 + ((u >> 3) & 1) * 2 + (u & 1);
        (m ? g_W1f : g_W0f)[n * 32 + fi] = *reinterpret_cast<uint32_t*>(&p);
    }

    if (tid < 16) tis[tid] = ti[b0 + tid];
    __syncthreads();
    for (int i = tid; i < 1024; i += 256) {
        int row = i >> 6, e = i & 63;
        float v = iemb[(long)tis[row] * EMB + e];
        ts[row][e] = v;
        g_x[(b0 + row) * 128 + 64 + e] = v;
    }
    __syncthreads();

    // c_b[b][n] = b1[n] + sum_e t[b][e] * (W1[64+e][n] - W1[128+e][n])
    const int n = tid;
    float acc[16];
    float bias = ab1[n];
    #pragma unroll
    for (int bb = 0; bb < 16; bb++) acc[bb] = bias;
    #pragma unroll 4
    for (int e = 0; e < 64; e++) {
        float m = aw1[(64 + e) * HID + n] - aw1[(128 + e) * HID + n];
        #pragma unroll
        for (int bb = 0; bb < 16; bb++) acc[bb] = fmaf(ts[bb][e], m, acc[bb]);
    }
    #pragma unroll
    for (int bb = 0; bb < 16; bb++) g_cb[(b0 + bb) * 256 + n] = acc[bb];
}

// ================= kernel 1: gather + fp8 GEMM (f16 acc) + softmax + pool =================
struct Smem1 {
    uint8_t A[208 * 80];              // h e4m3 x64, row stride 80 B
    __nv_bfloat16 pool[208 * 64];     // h bf16 for pooling (128 B rows)
    float t[64];
    float cb[256];
    float w2[256];
    float logits[208];
    float plog[8][208];               // per-warp partial logits; reused for pooling partials
    float red[16];
    int   idx[200];
};

__device__ __forceinline__ void mma_fp8_h(uint32_t& d0, uint32_t& d1,
                                          uint32_t a0, uint32_t a1, uint32_t a2, uint32_t a3,
                                          uint32_t b0, uint32_t b1) {
    asm volatile(
        "mma.sync.aligned.m16n8k32.row.col.f16.e4m3.e4m3.f16 "
        "{%0,%1}, {%2,%3,%4,%5}, {%6,%7}, {%0,%1};\n"
        : "+r"(d0), "+r"(d1)
        : "r"(a0), "r"(a1), "r"(a2), "r"(a3), "r"(b0), "r"(b1));
}

__device__ __forceinline__ uint32_t pack_e4m3_4(float a, float b, float c, float d) {
    __nv_fp8x2_storage_t lo = __nv_cvt_float2_to_fp8x2(make_float2(a, b), __NV_SATFINITE, __NV_E4M3);
    __nv_fp8x2_storage_t hi = __nv_cvt_float2_to_fp8x2(make_float2(c, d), __NV_SATFINITE, __NV_E4M3);
    return (uint32_t)lo | ((uint32_t)hi << 16);
}

__device__ __forceinline__ float2 bf2f2(uint32_t u) {
    return __bfloat1622float2(*reinterpret_cast<__nv_bfloat162*>(&u));
}

__global__ __launch_bounds__(256, 4) void din_main(
    const int* __restrict__ uh,
    const float* __restrict__ aw2)
{
    extern __shared__ char smraw[];
    Smem1& sm = *reinterpret_cast<Smem1*>(smraw);
    const int tid = threadIdx.x;
    const int b = blockIdx.x;
    const int warp = tid >> 5, lane = tid & 31;
    const int lr = lane >> 2, lc = lane & 3;
    uint32_t* PoolU = reinterpret_cast<uint32_t*>(sm.pool);

    // ---- stage indices, t, cb, w2; zero pads ----
    if (tid < 200) sm.idx[tid] = uh[b * SEQ + tid];
    if (tid >= 192) sm.t[tid - 192] = g_x[b * 128 + 64 + (tid - 192)];
    sm.cb[tid] = g_cb[b * 256 + tid];
    sm.w2[tid] = aw2[tid];
    if (tid < 160) reinterpret_cast<uint32_t*>(sm.A + 200 * 80)[tid] = 0u;  // pad rows 200..207
    __syncthreads();

    // ---- gather h (bf16 table): 1600 uint4 groups, front-batched ----
    {
        const uint4* ue = reinterpret_cast<const uint4*>(g_emb);   // 8 uint4 per row
        uint4 v[7];
        #pragma unroll
        for (int it = 0; it < 7; it++) {
            int i = tid + it * 256;
            if (i < 1600) v[it] = ue[(long)sm.idx[i >> 3] * 8 + (i & 7)];
        }
        #pragma unroll
        for (int it = 0; it < 7; it++) {
            int i = tid + it * 256;
            if (i < 1600) {
                int row = i >> 3, q = i & 7;
                uint4 vv = v[it];
                *reinterpret_cast<uint4*>(PoolU + row * 32 + q * 4) = vv;   // bf16 pool copy
                float2 f0 = bf2f2(vv.x), f1 = bf2f2(vv.y);
                float2 f2 = bf2f2(vv.z), f3 = bf2f2(vv.w);
                uint2 E;
                E.x = pack_e4m3_4(f0.x * FP8_SCALE, f0.y * FP8_SCALE,
                                  f1.x * FP8_SCALE, f1.y * FP8_SCALE);
                E.y = pack_e4m3_4(f2.x * FP8_SCALE, f2.y * FP8_SCALE,
                                  f3.x * FP8_SCALE, f3.y * FP8_SCALE);
                *reinterpret_cast<uint2*>(sm.A + row * 80 + q * 8) = E;
            }
        }
    }

    // ---- build fp8 B fragments: B_b = (W0 + t ∘ W1) * 64, fragment-ordered uint4 loads ----
    uint32_t Breg[4][2][2];   // [ntile][ks2][part]
    {
        const uint4* W0q = reinterpret_cast<const uint4*>(g_W0f);
        const uint4* W1q = reinterpret_cast<const uint4*>(g_W1f);
        #pragma unroll
        for (int nt = 0; nt < 4; nt++) {
            int nb = (warp * 4 + nt) * 8 + lr;
            int base = nb * 8 + lc * 2;
            uint4 q0a = W0q[base], q0b = W0q[base + 1];
            uint4 q1a = W1q[base], q1b = W1q[base + 1];
            #pragma unroll
            for (int half = 0; half < 4; half++) {
                uint32_t w0lo = half == 0 ? q0a.x : half == 1 ? q0a.z : half == 2 ? q0b.x : q0b.z;
                uint32_t w0hi = half == 0 ? q0a.y : half == 1 ? q0a.w : half == 2 ? q0b.y : q0b.w;
                uint32_t w1lo = half == 0 ? q1a.x : half == 1 ? q1a.z : half == 2 ? q1b.x : q1b.z;
                uint32_t w1hi = half == 0 ? q1a.y : half == 1 ? q1a.w : half == 2 ? q1b.y : q1b.w;
                int k0 = (half >> 1) * 32 + (half & 1) * 16 + lc * 4;
                float2 x0 = bf2f2(w0lo), x1 = bf2f2(w0hi);
                float2 y0 = bf2f2(w1lo), y1 = bf2f2(w1hi);
                float f0 = fmaf(sm.t[k0 + 0], y0.x, x0.x) * FP8_SCALE;
                float f1 = fmaf(sm.t[k0 + 1], y0.y, x0.y) * FP8_SCALE;
                float f2 = fmaf(sm.t[k0 + 2], y1.x, x1.x) * FP8_SCALE;
                float f3 = fmaf(sm.t[k0 + 3], y1.y, x1.y) * FP8_SCALE;
                Breg[nt][half >> 1][half & 1] = pack_e4m3_4(f0, f1, f2, f3);
            }
        }
    }
    __syncthreads();

    // ---- packed epilogue constants: cb*4096 and w2 as half2 pairs ----
    __half2 cbp[4], w2p[4];
    const __half2 z2 = __floats2half2_rn(0.f, 0.f);
    #pragma unroll
    for (int nt = 0; nt < 4; nt++) {
        int n0 = (warp * 4 + nt) * 8 + lc * 2;
        cbp[nt] = __floats2half2_rn(sm.cb[n0] * 4096.f, sm.cb[n0 + 1] * 4096.f);
        w2p[nt] = __floats2half2_rn(sm.w2[n0], sm.w2[n0 + 1]);
    }

    const uint32_t abase = (uint32_t)__cvta_generic_to_shared(sm.A);
    const uint32_t rowsel = (lane & 15);
    const uint32_t khalf  = (lane & 16) ? 16u : 0u;

    // ---- GEMM: 13 slabs x 4 n-tiles, f16 accumulators, packed epilogue ----
    #pragma unroll 1
    for (int slab = 0; slab < 13; slab++) {
        int r0 = slab * 16 + lr;
        uint32_t lmbase = abase + (slab * 16 + rowsel) * 80 + khalf;
        uint32_t a[2][4];
        #pragma unroll
        for (int ks2 = 0; ks2 < 2; ks2++) {
            asm volatile(
                "ldmatrix.sync.aligned.m8n8.x4.shared.b16 {%0,%1,%2,%3}, [%4];\n"
                : "=r"(a[ks2][0]), "=r"(a[ks2][1]), "=r"(a[ks2][2]), "=r"(a[ks2][3])
                : "r"(lmbase + ks2 * 32));
        }
        uint32_t d[4][2];
        #pragma unroll
        for (int nt = 0; nt < 4; nt++) d[nt][0] = d[nt][1] = 0u;
        #pragma unroll
        for (int ks2 = 0; ks2 < 2; ks2++) {
            #pragma unroll
            for (int nt = 0; nt < 4; nt++)
                mma_fp8_h(d[nt][0], d[nt][1],
                          a[ks2][0], a[ks2][1], a[ks2][2], a[ks2][3],
                          Breg[nt][ks2][0], Breg[nt][ks2][1]);
        }
        __half2 l0 = z2, l1 = z2;
        #pragma unroll
        for (int nt = 0; nt < 4; nt++) {
            __half2 d0 = *reinterpret_cast<__half2*>(&d[nt][0]);
            __half2 d1 = *reinterpret_cast<__half2*>(&d[nt][1]);
            l0 = __hfma2(__hmax2(__hadd2(d0, cbp[nt]), z2), w2p[nt], l0);
            l1 = __hfma2(__hmax2(__hadd2(d1, cbp[nt]), z2), w2p[nt], l1);
        }
        float lp0 = (__low2float(l0) + __high2float(l0)) * INV_SCALE;
        float lp1 = (__low2float(l1) + __high2float(l1)) * INV_SCALE;
        lp0 += __shfl_xor_sync(0xffffffffu, lp0, 1);
        lp0 += __shfl_xor_sync(0xffffffffu, lp0, 2);
        lp1 += __shfl_xor_sync(0xffffffffu, lp1, 1);
        lp1 += __shfl_xor_sync(0xffffffffu, lp1, 2);
        if (lc == 0) {
            sm.plog[warp][r0] = lp0;
            sm.plog[warp][r0 + 8] = lp1;
        }
    }
    __syncthreads();

    // ---- softmax over 200 logits (sum 8 warp-partials; no max-sub: |logit| << 1) ----
    {
        float v = 0.f;
        if (tid < SEQ) {
            #pragma unroll
            for (int w = 0; w < 8; w++) v += sm.plog[w][tid];
        }
        float ev = (tid < SEQ) ? __expf(v) : 0.f;
        float s = ev;
        #pragma unroll
        for (int o = 16; o > 0; o >>= 1) s += __shfl_xor_sync(0xffffffffu, s, o);
        if (lane == 0) sm.red[warp] = s;
        __syncthreads();
        if (tid == 0) {
            float ss = 0.f;
            #pragma unroll
            for (int w = 0; w < 8; w++) ss += sm.red[w];
            sm.red[8] = 1.f / ss;
        }
        __syncthreads();
        if (tid < SEQ) sm.logits[tid] = ev * sm.red[8];
    }
    __syncthreads();

    // ---- weighted pooling from bf16 pool tile (partials reuse plog space) ----
    float* part = &sm.plog[0][0];    // 8 chunks x 64 floats
    {
        int e2 = lane, chunk = warp;
        float acc0 = 0.f, acc1 = 0.f;
        int s0 = chunk * 25;
        #pragma unroll 5
        for (int s = s0; s < s0 + 25; s++) {
            float w = sm.logits[s];
            uint32_t u = PoolU[s * 32 + e2];
            __nv_bfloat162 h2 = *reinterpret_cast<__nv_bfloat162*>(&u);
            acc0 = fmaf(w, __bfloat162float(h2.x), acc0);
            acc1 = fmaf(w, __bfloat162float(h2.y), acc1);
        }
        part[chunk * 64 + e2 * 2]     = acc0;
        part[chunk * 64 + e2 * 2 + 1] = acc1;
    }
    __syncthreads();
    if (tid < 64) {
        float v = 0.f;
        #pragma unroll
        for (int c8 = 0; c8 < 8; c8++) v += part[c8 * 64 + tid];
        g_x[b * 128 + tid] = v;
    }
}

// ================= kernel 2: prediction head (fp16 weights, one wave) =================
struct Smem2 {
    uint32_t w1p[64 * 256];   // half2 pairs over k: (k=2j, 2j+1) for unit n -> w1p[j*256+n]
    float b1[256];
    float w2[256];
    float xs[16 * 128];       // 16 rows x 128
};

__global__ __launch_bounds__(256, 2) void din_mlp(
    const float* __restrict__ mw1, const float* __restrict__ mb1,
    const float* __restrict__ mw2, const float* __restrict__ mb2,
    float* __restrict__ out)
{
    extern __shared__ char smraw[];
    Smem2& sm = *reinterpret_cast<Smem2*>(smraw);
    const int tid = threadIdx.x;
    const int warp = tid >> 5, lane = tid & 31;

    // stage w1 as fp16 k-pairs: 4096 float4-pair groups, 16 per thread
    {
        const float4* W = reinterpret_cast<const float4*>(mw1);   // [128][64] float4
        #pragma unroll
        for (int it = 0; it < 16; it++) {
            int gi = tid + it * 256;
            int j = gi >> 6, n4 = gi & 63;
            float4 a = W[(2 * j) * 64 + n4];
            float4 c = W[(2 * j + 1) * 64 + n4];
            __half2 h0 = __floats2half2_rn(a.x, c.x);
            __half2 h1 = __floats2half2_rn(a.y, c.y);
            __half2 h2 = __floats2half2_rn(a.z, c.z);
            __half2 h3 = __floats2half2_rn(a.w, c.w);
            uint4 P;
            P.x = *reinterpret_cast<uint32_t*>(&h0);
            P.y = *reinterpret_cast<uint32_t*>(&h1);
            P.z = *reinterpret_cast<uint32_t*>(&h2);
            P.w = *reinterpret_cast<uint32_t*>(&h3);
            *reinterpret_cast<uint4*>(&sm.w1p[j * 256 + n4 * 4]) = P;
        }
    }
    sm.b1[tid] = mb1[tid];
    sm.w2[tid] = mw2[tid];
    // stage x: 16 rows x 32 float4 = 512 groups
    {
        const float4* gx4 = reinterpret_cast<const float4*>(g_x);
        float4* xs4 = reinterpret_cast<float4*>(sm.xs);
        xs4[tid]       = gx4[(long)blockIdx.x * 512 + tid];
        xs4[tid + 256] = gx4[(long)blockIdx.x * 512 + tid + 256];
    }
    __syncthreads();

    // warp handles 2 rows; thread owns units n = u*32+lane
    const int r0 = warp * 2, r1 = r0 + 1;
    float d0[8], d1[8];
    #pragma unroll
    for (int u = 0; u < 8; u++) d0[u] = d1[u] = sm.b1[u * 32 + lane];

    #pragma unroll 4
    for (int j = 0; j < 64; j++) {
        float2 x0 = *reinterpret_cast<const float2*>(&sm.xs[r0 * 128 + 2 * j]);
        float2 x1 = *reinterpret_cast<const float2*>(&sm.xs[r1 * 128 + 2 * j]);
        #pragma unroll
        for (int u = 0; u < 8; u++) {
            uint32_t wp = sm.w1p[j * 256 + u * 32 + lane];
            float2 w = __half22float2(*reinterpret_cast<__half2*>(&wp));
            d0[u] = fmaf(x0.x, w.x, fmaf(x0.y, w.y, d0[u]));
            d1[u] = fmaf(x1.x, w.x, fmaf(x1.y, w.y, d1[u]));
        }
    }

    float a0 = 0.f, a1 = 0.f;
    #pragma unroll
    for (int u = 0; u < 8; u++) {
        float w2v = sm.w2[u * 32 + lane];
        a0 += fmaxf(d0[u], 0.f) * w2v;
        a1 += fmaxf(d1[u], 0.f) * w2v;
    }
    #pragma unroll
    for (int o = 16; o > 0; o >>= 1) {
        a0 += __shfl_xor_sync(0xffffffffu, a0, o);
        a1 += __shfl_xor_sync(0xffffffffu, a1, o);
    }
    if (lane == 0) {
        float b2v = mb2[0];
        int row = blockIdx.x * 16 + r0;
        out[row]     = 1.f / (1.f + __expf(-(a0 + b2v)));
        out[row + 1] = 1.f / (1.f + __expf(-(a1 + b2v)));
    }
}

// ================= launch =================
extern "C" void kernel_launch(void* const* d_in, const int* in_sizes, int n_in,
                              void* d_out, int out_size) {
    const int*   uh   = (const int*)d_in[0];
    const int*   ti   = (const int*)d_in[1];
    const float* uemb = (const float*)d_in[2];
    const float* iemb = (const float*)d_in[3];
    const float* aw1  = (const float*)d_in[4];
    const float* ab1  = (const float*)d_in[5];
    const float* aw2  = (const float*)d_in[6];
    // d_in[7] attn_b2: softmax-invariant, unused
    const float* mw1  = (const float*)d_in[8];
    const float* mb1  = (const float*)d_in[9];
    const float* mw2  = (const float*)d_in[10];
    const float* mb2  = (const float*)d_in[11];
    float* out = (float*)d_out;

    cudaFuncSetAttribute(din_main, cudaFuncAttributeMaxDynamicSharedMemorySize, (int)sizeof(Smem1));
    cudaFuncSetAttribute(din_mlp,  cudaFuncAttributeMaxDynamicSharedMemorySize, (int)sizeof(Smem2));

    prep_conv<<<2048, 256>>>(uemb);
    prep_misc<<<256, 256>>>(aw1, ab1, ti, iemb);
    din_main<<<BATCH, 256, sizeof(Smem1)>>>(uh, aw2);
    din_mlp<<<256, 256, sizeof(Smem2)>>>(mw1, mb1, mw2, mb2, out);
}

// round 13
// speedup vs baseline: 1.8825x; 1.0407x over previous
#include <cuda_runtime.h>
#include <cuda_bf16.h>
#include <cuda_fp16.h>
#include <cuda_fp8.h>
#include <cstdint>

#define EMB 64
#define HID 256
#define SEQ 200
#define BATCH 4096
#define VOCAB 100000

// -------- device scratch (no allocations allowed) --------
__device__ __align__(16) __nv_bfloat16 g_emb[VOCAB * EMB]; // bf16 copy of user_emb (12.8 MB)
__device__ __align__(16) uint32_t g_W0f[256 * 32];         // W1[0:64]+W1[128:192], fragment-ordered bf16x2
__device__ __align__(16) uint32_t g_W1f[256 * 32];         // W1[192:256], fragment-ordered bf16x2
__device__ __align__(16) float g_Mt[64 * 256];             // W1[64:128]-W1[128:192], [e][n]
__device__ __align__(16) float g_cb[BATCH * 256];          // per-batch folded bias
__device__ __align__(16) float g_x[BATCH * 128];           // [interest | t] per batch row

#define FP8_SCALE 64.0f
#define INV_SCALE (1.0f / 4096.0f)

// ================= prep A: convert table to bf16 (ILP 4) + compute Mt =================
__global__ __launch_bounds__(256) void prep_conv(const float* __restrict__ uemb,
                                                 const float* __restrict__ aw1) {
    const float4* src = reinterpret_cast<const float4*>(uemb);
    uint2* dst = reinterpret_cast<uint2*>(g_emb);
    const int gid = blockIdx.x * 256 + threadIdx.x;         // 524288 threads
    const int total = VOCAB * EMB / 4;                      // 1.6M groups
    float4 v[4];
    #pragma unroll
    for (int s = 0; s < 4; s++) {
        int j = gid + s * 524288;
        if (j < total) v[s] = src[j];
    }
    #pragma unroll
    for (int s = 0; s < 4; s++) {
        int j = gid + s * 524288;
        if (j < total) {
            float4 vv = v[s];
            __nv_bfloat162 p0 = __floats2bfloat162_rn(vv.x, vv.y);
            __nv_bfloat162 p1 = __floats2bfloat162_rn(vv.z, vv.w);
            uint2 P;
            P.x = *reinterpret_cast<uint32_t*>(&p0);
            P.y = *reinterpret_cast<uint32_t*>(&p1);
            dst[j] = P;
        }
    }
    // Mt[e][n] (blocks 0..63)
    if (gid < 64 * 256) {
        int e = gid >> 8, n = gid & 255;
        g_Mt[gid] = aw1[(64 + e) * HID + n] - aw1[(128 + e) * HID + n];
    }
}

// ================= prep B: pack W fragments; compute c_b; stage t =================
// grid 512 x 256: block p handles batches [p*8, p*8+8); blocks <256 also pack a W slice
__global__ __launch_bounds__(256) void prep_misc(
    const float* __restrict__ aw1, const float* __restrict__ ab1,
    const int* __restrict__ ti, const float* __restrict__ iemb)
{
    __shared__ float ts[8][64];
    __shared__ int   tis[8];
    const int tid = threadIdx.x;
    const int b0 = blockIdx.x * 8;

    // pack W0f/W1f in per-lane fragment order: word u (k=2u,2u+1) of n-row n goes to
    // fi = ((u>>1)&3)*8 + (u>>4)*4 + ((u>>3)&1)*2 + (u&1)
    if (blockIdx.x < 256 && tid < 128) {
        int idx = blockIdx.x * 128 + tid;         // 0..32767
        int m = idx >> 14;                         // 0: W0, 1: W1
        int r = idx & 16383;
        int n = r >> 5, u = r & 31, k = u * 2;
        float v0, v1;
        if (m == 0) {
            v0 = aw1[k * HID + n] + aw1[(128 + k) * HID + n];
            v1 = aw1[(k + 1) * HID + n] + aw1[(129 + k) * HID + n];
        } else {
            v0 = aw1[(192 + k) * HID + n];
            v1 = aw1[(193 + k) * HID + n];
        }
        __nv_bfloat162 p = __floats2bfloat162_rn(v0, v1);
        int fi = ((u >> 1) & 3) * 8 + (u >> 4) * 4 + ((u >> 3) & 1) * 2 + (u & 1);
        (m ? g_W1f : g_W0f)[n * 32 + fi] = *reinterpret_cast<uint32_t*>(&p);
    }

    if (tid < 8) tis[tid] = ti[b0 + tid];
    __syncthreads();
    if (tid < 512 - 256) {}   // (no-op, keep shape)
    for (int i = tid; i < 512; i += 256) {
        int row = i >> 6, e = i & 63;
        float v = iemb[(long)tis[row] * EMB + e];
        ts[row][e] = v;
        g_x[(b0 + row) * 128 + 64 + e] = v;
    }
    __syncthreads();

    // c_b[b][n] = b1[n] + sum_e t[b][e] * Mt[e][n]
    const int n = tid;
    float acc[8];
    float bias = ab1[n];
    #pragma unroll
    for (int bb = 0; bb < 8; bb++) acc[bb] = bias;
    #pragma unroll 4
    for (int e = 0; e < 64; e++) {
        float m = g_Mt[e * 256 + n];
        #pragma unroll
        for (int bb = 0; bb < 8; bb++) acc[bb] = fmaf(ts[bb][e], m, acc[bb]);
    }
    #pragma unroll
    for (int bb = 0; bb < 8; bb++) g_cb[(b0 + bb) * 256 + n] = acc[bb];
}

// ================= kernel 1: gather + fp8 GEMM (f16 acc) + softmax + pool =================
struct Smem1 {
    uint8_t A[208 * 80];              // h e4m3 x64, row stride 80 B
    __nv_bfloat16 pool[208 * 64];     // h bf16 for pooling (128 B rows)
    float t[64];
    float cb[256];
    float w2[256];
    float logits[208];
    float plog[8][208];               // per-warp partial logits; reused for pooling partials
    float red[16];
    int   idx[200];
};

__device__ __forceinline__ void mma_fp8_h(uint32_t& d0, uint32_t& d1,
                                          uint32_t a0, uint32_t a1, uint32_t a2, uint32_t a3,
                                          uint32_t b0, uint32_t b1) {
    asm volatile(
        "mma.sync.aligned.m16n8k32.row.col.f16.e4m3.e4m3.f16 "
        "{%0,%1}, {%2,%3,%4,%5}, {%6,%7}, {%0,%1};\n"
        : "+r"(d0), "+r"(d1)
        : "r"(a0), "r"(a1), "r"(a2), "r"(a3), "r"(b0), "r"(b1));
}

__device__ __forceinline__ uint32_t pack_e4m3_4(float a, float b, float c, float d) {
    __nv_fp8x2_storage_t lo = __nv_cvt_float2_to_fp8x2(make_float2(a, b), __NV_SATFINITE, __NV_E4M3);
    __nv_fp8x2_storage_t hi = __nv_cvt_float2_to_fp8x2(make_float2(c, d), __NV_SATFINITE, __NV_E4M3);
    return (uint32_t)lo | ((uint32_t)hi << 16);
}

__device__ __forceinline__ float2 bf2f2(uint32_t u) {
    return __bfloat1622float2(*reinterpret_cast<__nv_bfloat162*>(&u));
}

__global__ __launch_bounds__(256, 4) void din_main(
    const int* __restrict__ uh,
    const float* __restrict__ aw2)
{
    extern __shared__ char smraw[];
    Smem1& sm = *reinterpret_cast<Smem1*>(smraw);
    const int tid = threadIdx.x;
    const int b = blockIdx.x;
    const int warp = tid >> 5, lane = tid & 31;
    const int lr = lane >> 2, lc = lane & 3;
    uint32_t* PoolU = reinterpret_cast<uint32_t*>(sm.pool);

    // ---- stage indices, t, cb, w2; zero pads ----
    if (tid < 200) sm.idx[tid] = uh[b * SEQ + tid];
    if (tid >= 192) sm.t[tid - 192] = g_x[b * 128 + 64 + (tid - 192)];
    sm.cb[tid] = g_cb[b * 256 + tid];
    sm.w2[tid] = aw2[tid];
    if (tid < 160) reinterpret_cast<uint32_t*>(sm.A + 200 * 80)[tid] = 0u;  // pad rows 200..207
    __syncthreads();

    // ---- gather h (bf16 table): 1600 uint4 groups, front-batched ----
    {
        const uint4* ue = reinterpret_cast<const uint4*>(g_emb);   // 8 uint4 per row
        uint4 v[7];
        #pragma unroll
        for (int it = 0; it < 7; it++) {
            int i = tid + it * 256;
            if (i < 1600) v[it] = ue[(long)sm.idx[i >> 3] * 8 + (i & 7)];
        }
        #pragma unroll
        for (int it = 0; it < 7; it++) {
            int i = tid + it * 256;
            if (i < 1600) {
                int row = i >> 3, q = i & 7;
                uint4 vv = v[it];
                *reinterpret_cast<uint4*>(PoolU + row * 32 + q * 4) = vv;   // bf16 pool copy
                float2 f0 = bf2f2(vv.x), f1 = bf2f2(vv.y);
                float2 f2 = bf2f2(vv.z), f3 = bf2f2(vv.w);
                uint2 E;
                E.x = pack_e4m3_4(f0.x * FP8_SCALE, f0.y * FP8_SCALE,
                                  f1.x * FP8_SCALE, f1.y * FP8_SCALE);
                E.y = pack_e4m3_4(f2.x * FP8_SCALE, f2.y * FP8_SCALE,
                                  f3.x * FP8_SCALE, f3.y * FP8_SCALE);
                *reinterpret_cast<uint2*>(sm.A + row * 80 + q * 8) = E;
            }
        }
    }

    // ---- build fp8 B fragments: B_b = (W0 + t ∘ W1) * 64, fragment-ordered uint4 loads ----
    uint32_t Breg[4][2][2];   // [ntile][ks2][part]
    {
        const uint4* W0q = reinterpret_cast<const uint4*>(g_W0f);
        const uint4* W1q = reinterpret_cast<const uint4*>(g_W1f);
        #pragma unroll
        for (int nt = 0; nt < 4; nt++) {
            int nb = (warp * 4 + nt) * 8 + lr;
            int base = nb * 8 + lc * 2;
            uint4 q0a = W0q[base], q0b = W0q[base + 1];
            uint4 q1a = W1q[base], q1b = W1q[base + 1];
            #pragma unroll
            for (int half = 0; half < 4; half++) {
                uint32_t w0lo = half == 0 ? q0a.x : half == 1 ? q0a.z : half == 2 ? q0b.x : q0b.z;
                uint32_t w0hi = half == 0 ? q0a.y : half == 1 ? q0a.w : half == 2 ? q0b.y : q0b.w;
                uint32_t w1lo = half == 0 ? q1a.x : half == 1 ? q1a.z : half == 2 ? q1b.x : q1b.z;
                uint32_t w1hi = half == 0 ? q1a.y : half == 1 ? q1a.w : half == 2 ? q1b.y : q1b.w;
                int k0 = (half >> 1) * 32 + (half & 1) * 16 + lc * 4;
                float2 x0 = bf2f2(w0lo), x1 = bf2f2(w0hi);
                float2 y0 = bf2f2(w1lo), y1 = bf2f2(w1hi);
                float f0 = fmaf(sm.t[k0 + 0], y0.x, x0.x) * FP8_SCALE;
                float f1 = fmaf(sm.t[k0 + 1], y0.y, x0.y) * FP8_SCALE;
                float f2 = fmaf(sm.t[k0 + 2], y1.x, x1.x) * FP8_SCALE;
                float f3 = fmaf(sm.t[k0 + 3], y1.y, x1.y) * FP8_SCALE;
                Breg[nt][half >> 1][half & 1] = pack_e4m3_4(f0, f1, f2, f3);
            }
        }
    }
    __syncthreads();

    // ---- packed epilogue constants: cb*4096 and w2 as half2 pairs ----
    __half2 cbp[4], w2p[4];
    const __half2 z2 = __floats2half2_rn(0.f, 0.f);
    #pragma unroll
    for (int nt = 0; nt < 4; nt++) {
        int n0 = (warp * 4 + nt) * 8 + lc * 2;
        cbp[nt] = __floats2half2_rn(sm.cb[n0] * 4096.f, sm.cb[n0 + 1] * 4096.f);
        w2p[nt] = __floats2half2_rn(sm.w2[n0], sm.w2[n0 + 1]);
    }

    const uint32_t abase = (uint32_t)__cvta_generic_to_shared(sm.A);
    const uint32_t rowsel = (lane & 15);
    const uint32_t khalf  = (lane & 16) ? 16u : 0u;

    // ---- GEMM: 13 slabs x 4 n-tiles, f16 accumulators, packed epilogue ----
    #pragma unroll 1
    for (int slab = 0; slab < 13; slab++) {
        int r0 = slab * 16 + lr;
        uint32_t lmbase = abase + (slab * 16 + rowsel) * 80 + khalf;
        uint32_t a[2][4];
        #pragma unroll
        for (int ks2 = 0; ks2 < 2; ks2++) {
            asm volatile(
                "ldmatrix.sync.aligned.m8n8.x4.shared.b16 {%0,%1,%2,%3}, [%4];\n"
                : "=r"(a[ks2][0]), "=r"(a[ks2][1]), "=r"(a[ks2][2]), "=r"(a[ks2][3])
                : "r"(lmbase + ks2 * 32));
        }
        uint32_t d[4][2];
        #pragma unroll
        for (int nt = 0; nt < 4; nt++) d[nt][0] = d[nt][1] = 0u;
        #pragma unroll
        for (int ks2 = 0; ks2 < 2; ks2++) {
            #pragma unroll
            for (int nt = 0; nt < 4; nt++)
                mma_fp8_h(d[nt][0], d[nt][1],
                          a[ks2][0], a[ks2][1], a[ks2][2], a[ks2][3],
                          Breg[nt][ks2][0], Breg[nt][ks2][1]);
        }
        __half2 l0 = z2, l1 = z2;
        #pragma unroll
        for (int nt = 0; nt < 4; nt++) {
            __half2 d0 = *reinterpret_cast<__half2*>(&d[nt][0]);
            __half2 d1 = *reinterpret_cast<__half2*>(&d[nt][1]);
            l0 = __hfma2(__hmax2(__hadd2(d0, cbp[nt]), z2), w2p[nt], l0);
            l1 = __hfma2(__hmax2(__hadd2(d1, cbp[nt]), z2), w2p[nt], l1);
        }
        // pack (row r0, row r0+8) partial logits into one half2, shfl-reduce over lc
        __half2 lp = __halves2half2(__hadd(__low2half(l0), __high2half(l0)),
                                    __hadd(__low2half(l1), __high2half(l1)));
        uint32_t lpu = *reinterpret_cast<uint32_t*>(&lp);
        #pragma unroll
        for (int o = 1; o <= 2; o <<= 1) {
            uint32_t other = __shfl_xor_sync(0xffffffffu, lpu, o);
            __half2 s = __hadd2(*reinterpret_cast<__half2*>(&lpu),
                                *reinterpret_cast<__half2*>(&other));
            lpu = *reinterpret_cast<uint32_t*>(&s);
        }
        if (lc == 0) {
            __half2 s = *reinterpret_cast<__half2*>(&lpu);
            sm.plog[warp][r0]     = __low2float(s) * INV_SCALE;
            sm.plog[warp][r0 + 8] = __high2float(s) * INV_SCALE;
        }
    }
    __syncthreads();

    // ---- softmax over 200 logits (sum 8 warp-partials; no max-sub: |logit| << 1) ----
    {
        float v = 0.f;
        if (tid < SEQ) {
            #pragma unroll
            for (int w = 0; w < 8; w++) v += sm.plog[w][tid];
        }
        float ev = (tid < SEQ) ? __expf(v) : 0.f;
        float s = ev;
        #pragma unroll
        for (int o = 16; o > 0; o >>= 1) s += __shfl_xor_sync(0xffffffffu, s, o);
        if (lane == 0) sm.red[warp] = s;
        __syncthreads();
        if (tid == 0) {
            float ss = 0.f;
            #pragma unroll
            for (int w = 0; w < 8; w++) ss += sm.red[w];
            sm.red[8] = 1.f / ss;
        }
        __syncthreads();
        if (tid < SEQ) sm.logits[tid] = ev * sm.red[8];
    }
    __syncthreads();

    // ---- weighted pooling from bf16 pool tile (partials reuse plog space) ----
    float* part = &sm.plog[0][0];    // 8 chunks x 64 floats
    {
        int e2 = lane, chunk = warp;
        float acc0 = 0.f, acc1 = 0.f;
        int s0 = chunk * 25;
        #pragma unroll 5
        for (int s = s0; s < s0 + 25; s++) {
            float w = sm.logits[s];
            uint32_t u = PoolU[s * 32 + e2];
            __nv_bfloat162 h2 = *reinterpret_cast<__nv_bfloat162*>(&u);
            acc0 = fmaf(w, __bfloat162float(h2.x), acc0);
            acc1 = fmaf(w, __bfloat162float(h2.y), acc1);
        }
        part[chunk * 64 + e2 * 2]     = acc0;
        part[chunk * 64 + e2 * 2 + 1] = acc1;
    }
    __syncthreads();
    if (tid < 64) {
        float v = 0.f;
        #pragma unroll
        for (int c8 = 0; c8 < 8; c8++) v += part[c8 * 64 + tid];
        g_x[b * 128 + tid] = v;
    }
}

// ================= kernel 2: prediction head (half2 / HFMA2, one wave) =================
struct Smem2 {
    uint4 w1q[128 * 32];      // [k][lane]: units 8*lane..8*lane+7 as 4 half2 (64 KB)
    __half2 b1h[128];         // unit pairs
    __half2 w2h[128];
    float xs[16 * 128];       // 16 rows x 128
};

__global__ __launch_bounds__(256, 2) void din_mlp(
    const float* __restrict__ mw1, const float* __restrict__ mb1,
    const float* __restrict__ mw2, const float* __restrict__ mb2,
    float* __restrict__ out)
{
    extern __shared__ char smraw[];
    Smem2& sm = *reinterpret_cast<Smem2*>(smraw);
    const int tid = threadIdx.x;
    const int warp = tid >> 5, lane = tid & 31;

    // stage w1 as [k][lane] uint4 of 4 half2 (units 8*lane..8*lane+7)
    {
        const float4* W = reinterpret_cast<const float4*>(mw1);   // [128][64] float4
        #pragma unroll
        for (int it = 0; it < 16; it++) {
            int gi = tid + it * 256;           // 4096 = 128k x 32lane
            int k = gi >> 5, l = gi & 31;
            float4 a = W[k * 64 + l * 2];
            float4 c = W[k * 64 + l * 2 + 1];
            __half2 h0 = __floats2half2_rn(a.x, a.y);
            __half2 h1 = __floats2half2_rn(a.z, a.w);
            __half2 h2 = __floats2half2_rn(c.x, c.y);
            __half2 h3 = __floats2half2_rn(c.z, c.w);
            uint4 P;
            P.x = *reinterpret_cast<uint32_t*>(&h0);
            P.y = *reinterpret_cast<uint32_t*>(&h1);
            P.z = *reinterpret_cast<uint32_t*>(&h2);
            P.w = *reinterpret_cast<uint32_t*>(&h3);
            sm.w1q[k * 32 + l] = P;
        }
    }
    if (tid < 128) {
        sm.b1h[tid] = __floats2half2_rn(mb1[2 * tid], mb1[2 * tid + 1]);
        sm.w2h[tid] = __floats2half2_rn(mw2[2 * tid], mw2[2 * tid + 1]);
    }
    // stage x: 16 rows x 32 float4 = 512 groups
    {
        const float4* gx4 = reinterpret_cast<const float4*>(g_x);
        float4* xs4 = reinterpret_cast<float4*>(sm.xs);
        xs4[tid]       = gx4[(long)blockIdx.x * 512 + tid];
        xs4[tid + 256] = gx4[(long)blockIdx.x * 512 + tid + 256];
    }
    __syncthreads();

    // warp handles 2 rows; lane owns 8 units as 4 half2 pairs
    const int r0 = warp * 2, r1 = r0 + 1;
    const __half2 z2 = __floats2half2_rn(0.f, 0.f);
    __half2 d0[4], d1[4];
    #pragma unroll
    for (int u = 0; u < 4; u++) d0[u] = d1[u] = z2;

    #pragma unroll 4
    for (int k = 0; k < 128; k++) {
        uint4 Wv = sm.w1q[k * 32 + lane];
        __half2 x0 = __float2half2_rn(sm.xs[r0 * 128 + k]);
        __half2 x1 = __float2half2_rn(sm.xs[r1 * 128 + k]);
        __half2 w0 = *reinterpret_cast<__half2*>(&Wv.x);
        __half2 w1 = *reinterpret_cast<__half2*>(&Wv.y);
        __half2 w2 = *reinterpret_cast<__half2*>(&Wv.z);
        __half2 w3 = *reinterpret_cast<__half2*>(&Wv.w);
        d0[0] = __hfma2(x0, w0, d0[0]);
        d0[1] = __hfma2(x0, w1, d0[1]);
        d0[2] = __hfma2(x0, w2, d0[2]);
        d0[3] = __hfma2(x0, w3, d0[3]);
        d1[0] = __hfma2(x1, w0, d1[0]);
        d1[1] = __hfma2(x1, w1, d1[1]);
        d1[2] = __hfma2(x1, w2, d1[2]);
        d1[3] = __hfma2(x1, w3, d1[3]);
    }

    __half2 acc0 = z2, acc1 = z2;
    #pragma unroll
    for (int u = 0; u < 4; u++) {
        __half2 bb  = sm.b1h[lane * 4 + u];
        __half2 ww  = sm.w2h[lane * 4 + u];
        acc0 = __hfma2(__hmax2(__hadd2(d0[u], bb), z2), ww, acc0);
        acc1 = __hfma2(__hmax2(__hadd2(d1[u], bb), z2), ww, acc1);
    }
    float a0 = __low2float(acc0) + __high2float(acc0);
    float a1 = __low2float(acc1) + __high2float(acc1);
    #pragma unroll
    for (int o = 16; o > 0; o >>= 1) {
        a0 += __shfl_xor_sync(0xffffffffu, a0, o);
        a1 += __shfl_xor_sync(0xffffffffu, a1, o);
    }
    if (lane == 0) {
        float b2v = mb2[0];
        int row = blockIdx.x * 16 + r0;
        out[row]     = 1.f / (1.f + __expf(-(a0 + b2v)));
        out[row + 1] = 1.f / (1.f + __expf(-(a1 + b2v)));
    }
}

// ================= launch =================
extern "C" void kernel_launch(void* const* d_in, const int* in_sizes, int n_in,
                              void* d_out, int out_size) {
    const int*   uh   = (const int*)d_in[0];
    const int*   ti   = (const int*)d_in[1];
    const float* uemb = (const float*)d_in[2];
    const float* iemb = (const float*)d_in[3];
    const float* aw1  = (const float*)d_in[4];
    const float* ab1  = (const float*)d_in[5];
    const float* aw2  = (const float*)d_in[6];
    // d_in[7] attn_b2: softmax-invariant, unused
    const float* mw1  = (const float*)d_in[8];
    const float* mb1  = (const float*)d_in[9];
    const float* mw2  = (const float*)d_in[10];
    const float* mb2  = (const float*)d_in[11];
    float* out = (float*)d_out;

    cudaFuncSetAttribute(din_main, cudaFuncAttributeMaxDynamicSharedMemorySize, (int)sizeof(Smem1));
    cudaFuncSetAttribute(din_mlp,  cudaFuncAttributeMaxDynamicSharedMemorySize, (int)sizeof(Smem2));

    prep_conv<<<2048, 256>>>(uemb, aw1);
    prep_misc<<<512, 256>>>(aw1, ab1, ti, iemb);
    din_main<<<BATCH, 256, sizeof(Smem1)>>>(uh, aw2);
    din_mlp<<<256, 256, sizeof(Smem2)>>>(mw1, mb1, mw2, mb2, out);
}

// round 15
// speedup vs baseline: 1.9453x; 1.0334x over previous
#include <cuda_runtime.h>
#include <cuda_bf16.h>
#include <cuda_fp16.h>
#include <cuda_fp8.h>
#include <cstdint>

#define EMB 64
#define HID 256
#define SEQ 200
#define BATCH 4096
#define VOCAB 100000

// -------- device scratch (no allocations allowed) --------
__device__ __align__(16) __nv_bfloat16 g_emb[VOCAB * EMB]; // bf16 copy of user_emb (12.8 MB)
__device__ __align__(16) uint32_t g_W0f[256 * 32];         // W1[0:64]+W1[128:192], fragment-ordered bf16x2
__device__ __align__(16) uint32_t g_W1f[256 * 32];         // W1[192:256], fragment-ordered bf16x2
__device__ __align__(16) __nv_bfloat16 g_mw1b[256 * 128];  // mlp_w1 transposed [n][k] bf16
__device__ __align__(16) float g_Mt[64 * 256];             // W1[64:128]-W1[128:192], [e][n]
__device__ __align__(16) float g_cb[BATCH * 256];          // per-batch folded bias
__device__ __align__(16) float g_x[BATCH * 128];           // [interest | t] per batch row

#define FP8_SCALE 64.0f
#define INV_SCALE (1.0f / 4096.0f)

// ================= prep A: convert table to bf16 (ILP 4) + Mt + mlp_w1 transpose =================
__global__ __launch_bounds__(256) void prep_conv(const float* __restrict__ uemb,
                                                 const float* __restrict__ aw1,
                                                 const float* __restrict__ mw1) {
    const float4* src = reinterpret_cast<const float4*>(uemb);
    uint2* dst = reinterpret_cast<uint2*>(g_emb);
    const int gid = blockIdx.x * 256 + threadIdx.x;         // 524288 threads
    const int total = VOCAB * EMB / 4;                      // 1.6M groups
    float4 v[4];
    #pragma unroll
    for (int s = 0; s < 4; s++) {
        int j = gid + s * 524288;
        if (j < total) v[s] = src[j];
    }
    #pragma unroll
    for (int s = 0; s < 4; s++) {
        int j = gid + s * 524288;
        if (j < total) {
            float4 vv = v[s];
            __nv_bfloat162 p0 = __floats2bfloat162_rn(vv.x, vv.y);
            __nv_bfloat162 p1 = __floats2bfloat162_rn(vv.z, vv.w);
            uint2 P;
            P.x = *reinterpret_cast<uint32_t*>(&p0);
            P.y = *reinterpret_cast<uint32_t*>(&p1);
            dst[j] = P;
        }
    }
    // Mt[e][n]
    if (gid < 64 * 256) {
        int e = gid >> 8, n = gid & 255;
        g_Mt[gid] = aw1[(64 + e) * HID + n] - aw1[(128 + e) * HID + n];
    }
    // mlp_w1 transpose -> [n][k] bf16
    if (gid < 128 * 256) {
        int k = gid >> 8, n = gid & 255;
        g_mw1b[n * 128 + k] = __float2bfloat16(mw1[gid]);
    }
}

// ================= prep B: pack W fragments; compute c_b; stage t =================
// grid 512 x 256: block p handles batches [p*8, p*8+8); blocks <256 also pack a W slice
__global__ __launch_bounds__(256) void prep_misc(
    const float* __restrict__ aw1, const float* __restrict__ ab1,
    const int* __restrict__ ti, const float* __restrict__ iemb)
{
    __shared__ float ts[8][64];
    __shared__ int   tis[8];
    const int tid = threadIdx.x;
    const int b0 = blockIdx.x * 8;

    // pack W0f/W1f in per-lane fragment order: word u (k=2u,2u+1) of n-row n goes to
    // fi = ((u>>1)&3)*8 + (u>>4)*4 + ((u>>3)&1)*2 + (u&1)
    if (blockIdx.x < 256 && tid < 128) {
        int idx = blockIdx.x * 128 + tid;         // 0..32767
        int m = idx >> 14;                         // 0: W0, 1: W1
        int r = idx & 16383;
        int n = r >> 5, u = r & 31, k = u * 2;
        float v0, v1;
        if (m == 0) {
            v0 = aw1[k * HID + n] + aw1[(128 + k) * HID + n];
            v1 = aw1[(k + 1) * HID + n] + aw1[(129 + k) * HID + n];
        } else {
            v0 = aw1[(192 + k) * HID + n];
            v1 = aw1[(193 + k) * HID + n];
        }
        __nv_bfloat162 p = __floats2bfloat162_rn(v0, v1);
        int fi = ((u >> 1) & 3) * 8 + (u >> 4) * 4 + ((u >> 3) & 1) * 2 + (u & 1);
        (m ? g_W1f : g_W0f)[n * 32 + fi] = *reinterpret_cast<uint32_t*>(&p);
    }

    if (tid < 8) tis[tid] = ti[b0 + tid];
    __syncthreads();
    for (int i = tid; i < 512; i += 256) {
        int row = i >> 6, e = i & 63;
        float v = iemb[(long)tis[row] * EMB + e];
        ts[row][e] = v;
        g_x[(b0 + row) * 128 + 64 + e] = v;
    }
    __syncthreads();

    // c_b[b][n] = b1[n] + sum_e t[b][e] * Mt[e][n]
    const int n = tid;
    float acc[8];
    float bias = ab1[n];
    #pragma unroll
    for (int bb = 0; bb < 8; bb++) acc[bb] = bias;
    #pragma unroll 4
    for (int e = 0; e < 64; e++) {
        float m = g_Mt[e * 256 + n];
        #pragma unroll
        for (int bb = 0; bb < 8; bb++) acc[bb] = fmaf(ts[bb][e], m, acc[bb]);
    }
    #pragma unroll
    for (int bb = 0; bb < 8; bb++) g_cb[(b0 + bb) * 256 + n] = acc[bb];
}

// ================= kernel 1: gather + fp8 GEMM (f16 acc) + softmax + pool =================
struct Smem1 {
    uint8_t A[208 * 80];              // h e4m3 x64, row stride 80 B
    __nv_bfloat16 pool[208 * 64];     // h bf16 for pooling (128 B rows)
    float t[64];
    float cb[256];
    float w2[256];
    float logits[208];
    float plog[8][208];               // per-warp partial logits; reused for pooling partials
    float red[16];
    int   idx[200];
};

__device__ __forceinline__ void mma_fp8_h(uint32_t& d0, uint32_t& d1,
                                          uint32_t a0, uint32_t a1, uint32_t a2, uint32_t a3,
                                          uint32_t b0, uint32_t b1) {
    asm volatile(
        "mma.sync.aligned.m16n8k32.row.col.f16.e4m3.e4m3.f16 "
        "{%0,%1}, {%2,%3,%4,%5}, {%6,%7}, {%0,%1};\n"
        : "+r"(d0), "+r"(d1)
        : "r"(a0), "r"(a1), "r"(a2), "r"(a3), "r"(b0), "r"(b1));
}

__device__ __forceinline__ void mma16816(float& c0, float& c1, float& c2, float& c3,
                                         uint32_t a0, uint32_t a1, uint32_t a2, uint32_t a3,
                                         uint32_t b0, uint32_t b1) {
    asm volatile(
        "mma.sync.aligned.m16n8k16.row.col.f32.bf16.bf16.f32 "
        "{%0,%1,%2,%3}, {%4,%5,%6,%7}, {%8,%9}, {%0,%1,%2,%3};\n"
        : "+f"(c0), "+f"(c1), "+f"(c2), "+f"(c3)
        : "r"(a0), "r"(a1), "r"(a2), "r"(a3), "r"(b0), "r"(b1));
}

__device__ __forceinline__ uint32_t pack_e4m3_4(float a, float b, float c, float d) {
    __nv_fp8x2_storage_t lo = __nv_cvt_float2_to_fp8x2(make_float2(a, b), __NV_SATFINITE, __NV_E4M3);
    __nv_fp8x2_storage_t hi = __nv_cvt_float2_to_fp8x2(make_float2(c, d), __NV_SATFINITE, __NV_E4M3);
    return (uint32_t)lo | ((uint32_t)hi << 16);
}

__device__ __forceinline__ float2 bf2f2(uint32_t u) {
    return __bfloat1622float2(*reinterpret_cast<__nv_bfloat162*>(&u));
}

__global__ __launch_bounds__(256, 4) void din_main(
    const int* __restrict__ uh,
    const float* __restrict__ aw2)
{
    extern __shared__ char smraw[];
    Smem1& sm = *reinterpret_cast<Smem1*>(smraw);
    const int tid = threadIdx.x;
    const int b = blockIdx.x;
    const int warp = tid >> 5, lane = tid & 31;
    const int lr = lane >> 2, lc = lane & 3;
    uint32_t* PoolU = reinterpret_cast<uint32_t*>(sm.pool);

    // ---- stage indices, t, cb, w2; zero pads ----
    if (tid < 200) sm.idx[tid] = uh[b * SEQ + tid];
    if (tid >= 192) sm.t[tid - 192] = g_x[b * 128 + 64 + (tid - 192)];
    sm.cb[tid] = g_cb[b * 256 + tid];
    sm.w2[tid] = aw2[tid];
    if (tid < 160) reinterpret_cast<uint32_t*>(sm.A + 200 * 80)[tid] = 0u;  // pad rows 200..207
    __syncthreads();

    // ---- gather h (bf16 table): 1600 uint4 groups, front-batched ----
    {
        const uint4* ue = reinterpret_cast<const uint4*>(g_emb);   // 8 uint4 per row
        uint4 v[7];
        #pragma unroll
        for (int it = 0; it < 7; it++) {
            int i = tid + it * 256;
            if (i < 1600) v[it] = ue[(long)sm.idx[i >> 3] * 8 + (i & 7)];
        }
        #pragma unroll
        for (int it = 0; it < 7; it++) {
            int i = tid + it * 256;
            if (i < 1600) {
                int row = i >> 3, q = i & 7;
                uint4 vv = v[it];
                *reinterpret_cast<uint4*>(PoolU + row * 32 + q * 4) = vv;   // bf16 pool copy
                float2 f0 = bf2f2(vv.x), f1 = bf2f2(vv.y);
                float2 f2 = bf2f2(vv.z), f3 = bf2f2(vv.w);
                uint2 E;
                E.x = pack_e4m3_4(f0.x * FP8_SCALE, f0.y * FP8_SCALE,
                                  f1.x * FP8_SCALE, f1.y * FP8_SCALE);
                E.y = pack_e4m3_4(f2.x * FP8_SCALE, f2.y * FP8_SCALE,
                                  f3.x * FP8_SCALE, f3.y * FP8_SCALE);
                *reinterpret_cast<uint2*>(sm.A + row * 80 + q * 8) = E;
            }
        }
    }

    // ---- build fp8 B fragments: B_b = (W0 + t ∘ W1) * 64, fragment-ordered uint4 loads ----
    uint32_t Breg[4][2][2];   // [ntile][ks2][part]
    {
        const uint4* W0q = reinterpret_cast<const uint4*>(g_W0f);
        const uint4* W1q = reinterpret_cast<const uint4*>(g_W1f);
        #pragma unroll
        for (int nt = 0; nt < 4; nt++) {
            int nb = (warp * 4 + nt) * 8 + lr;
            int base = nb * 8 + lc * 2;
            uint4 q0a = W0q[base], q0b = W0q[base + 1];
            uint4 q1a = W1q[base], q1b = W1q[base + 1];
            #pragma unroll
            for (int half = 0; half < 4; half++) {
                uint32_t w0lo = half == 0 ? q0a.x : half == 1 ? q0a.z : half == 2 ? q0b.x : q0b.z;
                uint32_t w0hi = half == 0 ? q0a.y : half == 1 ? q0a.w : half == 2 ? q0b.y : q0b.w;
                uint32_t w1lo = half == 0 ? q1a.x : half == 1 ? q1a.z : half == 2 ? q1b.x : q1b.z;
                uint32_t w1hi = half == 0 ? q1a.y : half == 1 ? q1a.w : half == 2 ? q1b.y : q1b.w;
                int k0 = (half >> 1) * 32 + (half & 1) * 16 + lc * 4;
                float2 x0 = bf2f2(w0lo), x1 = bf2f2(w0hi);
                float2 y0 = bf2f2(w1lo), y1 = bf2f2(w1hi);
                float f0 = fmaf(sm.t[k0 + 0], y0.x, x0.x) * FP8_SCALE;
                float f1 = fmaf(sm.t[k0 + 1], y0.y, x0.y) * FP8_SCALE;
                float f2 = fmaf(sm.t[k0 + 2], y1.x, x1.x) * FP8_SCALE;
                float f3 = fmaf(sm.t[k0 + 3], y1.y, x1.y) * FP8_SCALE;
                Breg[nt][half >> 1][half & 1] = pack_e4m3_4(f0, f1, f2, f3);
            }
        }
    }
    __syncthreads();

    // ---- packed epilogue constants: cb*4096 and w2 as half2 pairs ----
    __half2 cbp[4], w2p[4];
    const __half2 z2 = __floats2half2_rn(0.f, 0.f);
    #pragma unroll
    for (int nt = 0; nt < 4; nt++) {
        int n0 = (warp * 4 + nt) * 8 + lc * 2;
        cbp[nt] = __floats2half2_rn(sm.cb[n0] * 4096.f, sm.cb[n0 + 1] * 4096.f);
        w2p[nt] = __floats2half2_rn(sm.w2[n0], sm.w2[n0 + 1]);
    }

    const uint32_t abase = (uint32_t)__cvta_generic_to_shared(sm.A);
    const uint32_t rowsel = (lane & 15);
    const uint32_t khalf  = (lane & 16) ? 16u : 0u;

    // ---- GEMM: 13 slabs x 4 n-tiles, f16 accumulators, packed epilogue ----
    #pragma unroll 1
    for (int slab = 0; slab < 13; slab++) {
        int r0 = slab * 16 + lr;
        uint32_t lmbase = abase + (slab * 16 + rowsel) * 80 + khalf;
        uint32_t a[2][4];
        #pragma unroll
        for (int ks2 = 0; ks2 < 2; ks2++) {
            asm volatile(
                "ldmatrix.sync.aligned.m8n8.x4.shared.b16 {%0,%1,%2,%3}, [%4];\n"
                : "=r"(a[ks2][0]), "=r"(a[ks2][1]), "=r"(a[ks2][2]), "=r"(a[ks2][3])
                : "r"(lmbase + ks2 * 32));
        }
        uint32_t d[4][2];
        #pragma unroll
        for (int nt = 0; nt < 4; nt++) d[nt][0] = d[nt][1] = 0u;
        #pragma unroll
        for (int ks2 = 0; ks2 < 2; ks2++) {
            #pragma unroll
            for (int nt = 0; nt < 4; nt++)
                mma_fp8_h(d[nt][0], d[nt][1],
                          a[ks2][0], a[ks2][1], a[ks2][2], a[ks2][3],
                          Breg[nt][ks2][0], Breg[nt][ks2][1]);
        }
        __half2 l0 = z2, l1 = z2;
        #pragma unroll
        for (int nt = 0; nt < 4; nt++) {
            __half2 d0 = *reinterpret_cast<__half2*>(&d[nt][0]);
            __half2 d1 = *reinterpret_cast<__half2*>(&d[nt][1]);
            l0 = __hfma2(__hmax2(__hadd2(d0, cbp[nt]), z2), w2p[nt], l0);
            l1 = __hfma2(__hmax2(__hadd2(d1, cbp[nt]), z2), w2p[nt], l1);
        }
        // pack (row r0, row r0+8) partial logits into one half2, shfl-reduce over lc
        __half2 lp = __halves2half2(__hadd(__low2half(l0), __high2half(l0)),
                                    __hadd(__low2half(l1), __high2half(l1)));
        uint32_t lpu = *reinterpret_cast<uint32_t*>(&lp);
        #pragma unroll
        for (int o = 1; o <= 2; o <<= 1) {
            uint32_t other = __shfl_xor_sync(0xffffffffu, lpu, o);
            __half2 s = __hadd2(*reinterpret_cast<__half2*>(&lpu),
                                *reinterpret_cast<__half2*>(&other));
            lpu = *reinterpret_cast<uint32_t*>(&s);
        }
        if (lc == 0) {
            __half2 s = *reinterpret_cast<__half2*>(&lpu);
            sm.plog[warp][r0]     = __low2float(s) * INV_SCALE;
            sm.plog[warp][r0 + 8] = __high2float(s) * INV_SCALE;
        }
    }
    __syncthreads();

    // ---- softmax over 200 logits (sum 8 warp-partials; no max-sub: |logit| << 1) ----
    {
        float v = 0.f;
        if (tid < SEQ) {
            #pragma unroll
            for (int w = 0; w < 8; w++) v += sm.plog[w][tid];
        }
        float ev = (tid < SEQ) ? __expf(v) : 0.f;
        float s = ev;
        #pragma unroll
        for (int o = 16; o > 0; o >>= 1) s += __shfl_xor_sync(0xffffffffu, s, o);
        if (lane == 0) sm.red[warp] = s;
        __syncthreads();
        if (tid == 0) {
            float ss = 0.f;
            #pragma unroll
            for (int w = 0; w < 8; w++) ss += sm.red[w];
            sm.red[8] = 1.f / ss;
        }
        __syncthreads();
        if (tid < SEQ) sm.logits[tid] = ev * sm.red[8];
    }
    __syncthreads();

    // ---- weighted pooling from bf16 pool tile (partials reuse plog space) ----
    float* part = &sm.plog[0][0];    // 8 chunks x 64 floats
    {
        int e2 = lane, chunk = warp;
        float acc0 = 0.f, acc1 = 0.f;
        int s0 = chunk * 25;
        #pragma unroll 5
        for (int s = s0; s < s0 + 25; s++) {
            float w = sm.logits[s];
            uint32_t u = PoolU[s * 32 + e2];
            __nv_bfloat162 h2 = *reinterpret_cast<__nv_bfloat162*>(&u);
            acc0 = fmaf(w, __bfloat162float(h2.x), acc0);
            acc1 = fmaf(w, __bfloat162float(h2.y), acc1);
        }
        part[chunk * 64 + e2 * 2]     = acc0;
        part[chunk * 64 + e2 * 2 + 1] = acc1;
    }
    __syncthreads();
    if (tid < 64) {
        float v = 0.f;
        #pragma unroll
        for (int c8 = 0; c8 < 8; c8++) v += part[c8 * 64 + tid];
        g_x[b * 128 + tid] = v;
    }
}

// ================= kernel 2: prediction head via PROVEN bf16/f32 mma (64 rows/block) =================
struct Smem3 {
    __nv_bfloat16 xh[64 * 136];   // x bf16, row stride 136 halves (272 B)
    float b1s[256];
    float w2s[256];
    float plog[8][64];            // per-warp partial z
};

__global__ __launch_bounds__(256, 1) void din_mlp(
    const float* __restrict__ mb1,
    const float* __restrict__ mw2, const float* __restrict__ mb2,
    float* __restrict__ out)
{
    extern __shared__ char smraw[];
    Smem3& sm = *reinterpret_cast<Smem3*>(smraw);
    const int tid = threadIdx.x;
    const int warp = tid >> 5, lane = tid & 31;
    const int lr = lane >> 2, lc = lane & 3;
    const int b0 = blockIdx.x * 64;

    // ---- stage x [64 x 128] fp32 -> bf16 (stride 136 halves) ----
    {
        const float4* gx4 = reinterpret_cast<const float4*>(g_x);
        #pragma unroll
        for (int it = 0; it < 8; it++) {
            int i = tid + it * 256;          // 0..2047 = 64 rows x 32 float4
            int row = i >> 5, q = i & 31;
            float4 v = gx4[(long)b0 * 32 + i];
            __nv_bfloat162 h0 = __floats2bfloat162_rn(v.x, v.y);
            __nv_bfloat162 h1 = __floats2bfloat162_rn(v.z, v.w);
            uint2 P;
            P.x = *reinterpret_cast<uint32_t*>(&h0);
            P.y = *reinterpret_cast<uint32_t*>(&h1);
            *reinterpret_cast<uint2*>(&sm.xh[row * 136 + q * 4]) = P;
        }
    }
    sm.b1s[tid] = mb1[tid];
    sm.w2s[tid] = mw2[tid];

    // ---- B fragments: warp's 4 n-tiles x 8 k-steps from g_mw1b [n][k] bf16 ----
    uint32_t Breg[4][8][2];
    {
        const uint32_t* Wg = reinterpret_cast<const uint32_t*>(g_mw1b);
        #pragma unroll
        for (int nt = 0; nt < 4; nt++) {
            int n = (warp * 4 + nt) * 8 + lr;
            #pragma unroll
            for (int ks = 0; ks < 8; ks++) {
                Breg[nt][ks][0] = Wg[n * 64 + ks * 8 + lc];
                Breg[nt][ks][1] = Wg[n * 64 + ks * 8 + lc + 4];
            }
        }
    }
    __syncthreads();

    // f32 epilogue constants (round-4-proven pattern)
    float b1v[4][2], w2v[4][2];
    #pragma unroll
    for (int nt = 0; nt < 4; nt++) {
        int n0 = (warp * 4 + nt) * 8 + lc * 2;
        b1v[nt][0] = sm.b1s[n0];     b1v[nt][1] = sm.b1s[n0 + 1];
        w2v[nt][0] = sm.w2s[n0];     w2v[nt][1] = sm.w2s[n0 + 1];
    }

    const uint32_t abase = (uint32_t)__cvta_generic_to_shared(sm.xh);
    const uint32_t rowsel = (lane & 15);
    const uint32_t khalf  = (lane & 16) ? 16u : 0u;

    // ---- GEMM: 4 slabs x 4 n-tiles x 8 k-steps, f32 accumulate ----
    #pragma unroll 1
    for (int slab = 0; slab < 4; slab++) {
        int r0 = slab * 16 + lr;
        uint32_t lmbase = abase + (slab * 16 + rowsel) * 272 + khalf;
        uint32_t a[8][4];
        #pragma unroll
        for (int ks = 0; ks < 8; ks++) {
            asm volatile(
                "ldmatrix.sync.aligned.m8n8.x4.shared.b16 {%0,%1,%2,%3}, [%4];\n"
                : "=r"(a[ks][0]), "=r"(a[ks][1]), "=r"(a[ks][2]), "=r"(a[ks][3])
                : "r"(lmbase + ks * 32));
        }
        float lp0 = 0.f, lp1 = 0.f;
        #pragma unroll
        for (int nt = 0; nt < 4; nt++) {
            float c0 = 0.f, c1 = 0.f, c2 = 0.f, c3 = 0.f;
            #pragma unroll
            for (int ks = 0; ks < 8; ks++)
                mma16816(c0, c1, c2, c3,
                         a[ks][0], a[ks][1], a[ks][2], a[ks][3],
                         Breg[nt][ks][0], Breg[nt][ks][1]);
            lp0 += fmaxf(c0 + b1v[nt][0], 0.f) * w2v[nt][0]
                 + fmaxf(c1 + b1v[nt][1], 0.f) * w2v[nt][1];
            lp1 += fmaxf(c2 + b1v[nt][0], 0.f) * w2v[nt][0]
                 + fmaxf(c3 + b1v[nt][1], 0.f) * w2v[nt][1];
        }
        lp0 += __shfl_xor_sync(0xffffffffu, lp0, 1);
        lp0 += __shfl_xor_sync(0xffffffffu, lp0, 2);
        lp1 += __shfl_xor_sync(0xffffffffu, lp1, 1);
        lp1 += __shfl_xor_sync(0xffffffffu, lp1, 2);
        if (lc == 0) {
            sm.plog[warp][r0]     = lp0;
            sm.plog[warp][r0 + 8] = lp1;
        }
    }
    __syncthreads();

    if (tid < 64) {
        float z = mb2[0];
        #pragma unroll
        for (int w = 0; w < 8; w++) z += sm.plog[w][tid];
        out[b0 + tid] = 1.f / (1.f + __expf(-z));
    }
}

// ================= launch =================
extern "C" void kernel_launch(void* const* d_in, const int* in_sizes, int n_in,
                              void* d_out, int out_size) {
    const int*   uh   = (const int*)d_in[0];
    const int*   ti   = (const int*)d_in[1];
    const float* uemb = (const float*)d_in[2];
    const float* iemb = (const float*)d_in[3];
    const float* aw1  = (const float*)d_in[4];
    const float* ab1  = (const float*)d_in[5];
    const float* aw2  = (const float*)d_in[6];
    // d_in[7] attn_b2: softmax-invariant, unused
    const float* mw1  = (const float*)d_in[8];
    const float* mb1  = (const float*)d_in[9];
    const float* mw2  = (const float*)d_in[10];
    const float* mb2  = (const float*)d_in[11];
    float* out = (float*)d_out;

    cudaFuncSetAttribute(din_main, cudaFuncAttributeMaxDynamicSharedMemorySize, (int)sizeof(Smem1));
    cudaFuncSetAttribute(din_mlp,  cudaFuncAttributeMaxDynamicSharedMemorySize, (int)sizeof(Smem3));

    prep_conv<<<2048, 256>>>(uemb, aw1, mw1);
    prep_misc<<<512, 256>>>(aw1, ab1, ti, iemb);
    din_main<<<BATCH, 256, sizeof(Smem1)>>>(uh, aw2);
    din_mlp<<<64, 256, sizeof(Smem3)>>>(mb1, mw2, mb2, out);
}

// round 17
// speedup vs baseline: 1.9734x; 1.0145x over previous
#include <cuda_runtime.h>
#include <cuda_bf16.h>
#include <cuda_fp16.h>
#include <cuda_fp8.h>
#include <cstdint>

#define EMB 64
#define HID 256
#define SEQ 200
#define BATCH 4096
#define VOCAB 100000

// -------- device scratch (no allocations allowed) --------
__device__ __align__(16) __nv_bfloat16 g_emb[VOCAB * EMB]; // bf16 copy of user_emb (12.8 MB)
__device__ __align__(16) uint32_t g_W0f[256 * 32];         // W1[0:64]+W1[128:192], fragment-ordered bf16x2
__device__ __align__(16) uint32_t g_W1f[256 * 32];         // W1[192:256], fragment-ordered bf16x2
__device__ __align__(16) __nv_bfloat16 g_mw1b[256 * 128];  // mlp_w1 transposed [n][k] bf16
__device__ __align__(16) float g_Mt[64 * 256];             // W1[64:128]-W1[128:192], [e][n]
__device__ __align__(16) float g_cb[BATCH * 256];          // per-batch folded bias
__device__ __align__(16) float g_x[BATCH * 128];           // [interest | t] per batch row

#define FP8_SCALE 64.0f
#define INV_SCALE (1.0f / 4096.0f)

// ================= prep A: convert table to bf16 (ILP 4) + Mt + mlp_w1 transpose =================
__global__ __launch_bounds__(256) void prep_conv(const float* __restrict__ uemb,
                                                 const float* __restrict__ aw1,
                                                 const float* __restrict__ mw1) {
    const float4* src = reinterpret_cast<const float4*>(uemb);
    uint2* dst = reinterpret_cast<uint2*>(g_emb);
    const int gid = blockIdx.x * 256 + threadIdx.x;         // 524288 threads
    const int total = VOCAB * EMB / 4;                      // 1.6M groups
    float4 v[4];
    #pragma unroll
    for (int s = 0; s < 4; s++) {
        int j = gid + s * 524288;
        if (j < total) v[s] = src[j];
    }
    #pragma unroll
    for (int s = 0; s < 4; s++) {
        int j = gid + s * 524288;
        if (j < total) {
            float4 vv = v[s];
            __nv_bfloat162 p0 = __floats2bfloat162_rn(vv.x, vv.y);
            __nv_bfloat162 p1 = __floats2bfloat162_rn(vv.z, vv.w);
            uint2 P;
            P.x = *reinterpret_cast<uint32_t*>(&p0);
            P.y = *reinterpret_cast<uint32_t*>(&p1);
            dst[j] = P;
        }
    }
    // Mt[e][n]
    if (gid < 64 * 256) {
        int e = gid >> 8, n = gid & 255;
        g_Mt[gid] = aw1[(64 + e) * HID + n] - aw1[(128 + e) * HID + n];
    }
    // mlp_w1 transpose -> [n][k] bf16
    if (gid < 128 * 256) {
        int k = gid >> 8, n = gid & 255;
        g_mw1b[n * 128 + k] = __float2bfloat16(mw1[gid]);
    }
}

// ================= prep B: pack W fragments; compute c_b; stage t =================
// grid 512 x 256: block p handles batches [p*8, p*8+8); blocks <256 also pack a W slice
__global__ __launch_bounds__(256) void prep_misc(
    const float* __restrict__ aw1, const float* __restrict__ ab1,
    const int* __restrict__ ti, const float* __restrict__ iemb)
{
    __shared__ float ts[8][64];
    __shared__ int   tis[8];
    const int tid = threadIdx.x;
    const int b0 = blockIdx.x * 8;

    // pack W0f/W1f in per-lane fragment order: word u (k=2u,2u+1) of n-row n goes to
    // fi = ((u>>1)&3)*8 + (u>>4)*4 + ((u>>3)&1)*2 + (u&1)
    if (blockIdx.x < 256 && tid < 128) {
        int idx = blockIdx.x * 128 + tid;         // 0..32767
        int m = idx >> 14;                         // 0: W0, 1: W1
        int r = idx & 16383;
        int n = r >> 5, u = r & 31, k = u * 2;
        float v0, v1;
        if (m == 0) {
            v0 = aw1[k * HID + n] + aw1[(128 + k) * HID + n];
            v1 = aw1[(k + 1) * HID + n] + aw1[(129 + k) * HID + n];
        } else {
            v0 = aw1[(192 + k) * HID + n];
            v1 = aw1[(193 + k) * HID + n];
        }
        __nv_bfloat162 p = __floats2bfloat162_rn(v0, v1);
        int fi = ((u >> 1) & 3) * 8 + (u >> 4) * 4 + ((u >> 3) & 1) * 2 + (u & 1);
        (m ? g_W1f : g_W0f)[n * 32 + fi] = *reinterpret_cast<uint32_t*>(&p);
    }

    if (tid < 8) tis[tid] = ti[b0 + tid];
    __syncthreads();
    for (int i = tid; i < 512; i += 256) {
        int row = i >> 6, e = i & 63;
        float v = iemb[(long)tis[row] * EMB + e];
        ts[row][e] = v;
        g_x[(b0 + row) * 128 + 64 + e] = v;
    }
    __syncthreads();

    // c_b[b][n] = b1[n] + sum_e t[b][e] * Mt[e][n]
    const int n = tid;
    float acc[8];
    float bias = ab1[n];
    #pragma unroll
    for (int bb = 0; bb < 8; bb++) acc[bb] = bias;
    #pragma unroll 4
    for (int e = 0; e < 64; e++) {
        float m = g_Mt[e * 256 + n];
        #pragma unroll
        for (int bb = 0; bb < 8; bb++) acc[bb] = fmaf(ts[bb][e], m, acc[bb]);
    }
    #pragma unroll
    for (int bb = 0; bb < 8; bb++) g_cb[(b0 + bb) * 256 + n] = acc[bb];
}

// ================= kernel 1: gather + fp8 GEMM (f16 acc) + softmax + pool =================
struct Smem1 {
    uint8_t A[208 * 80];              // h e4m3 x64, row stride 80 B
    __nv_bfloat16 pool[208 * 64];     // h bf16 for pooling (128 B rows)
    float t[64];
    float cb[256];
    float w2[256];
    float logits[208];
    float plog[8][208];               // per-warp partial logits; reused for pooling partials
    float red[16];
    int   idx[200];
};

__device__ __forceinline__ void mma_fp8_h(uint32_t& d0, uint32_t& d1,
                                          uint32_t a0, uint32_t a1, uint32_t a2, uint32_t a3,
                                          uint32_t b0, uint32_t b1) {
    asm volatile(
        "mma.sync.aligned.m16n8k32.row.col.f16.e4m3.e4m3.f16 "
        "{%0,%1}, {%2,%3,%4,%5}, {%6,%7}, {%0,%1};\n"
        : "+r"(d0), "+r"(d1)
        : "r"(a0), "r"(a1), "r"(a2), "r"(a3), "r"(b0), "r"(b1));
}

__device__ __forceinline__ void mma16816(float& c0, float& c1, float& c2, float& c3,
                                         uint32_t a0, uint32_t a1, uint32_t a2, uint32_t a3,
                                         uint32_t b0, uint32_t b1) {
    asm volatile(
        "mma.sync.aligned.m16n8k16.row.col.f32.bf16.bf16.f32 "
        "{%0,%1,%2,%3}, {%4,%5,%6,%7}, {%8,%9}, {%0,%1,%2,%3};\n"
        : "+f"(c0), "+f"(c1), "+f"(c2), "+f"(c3)
        : "r"(a0), "r"(a1), "r"(a2), "r"(a3), "r"(b0), "r"(b1));
}

__device__ __forceinline__ uint32_t pack_e4m3_4(float a, float b, float c, float d) {
    __nv_fp8x2_storage_t lo = __nv_cvt_float2_to_fp8x2(make_float2(a, b), __NV_SATFINITE, __NV_E4M3);
    __nv_fp8x2_storage_t hi = __nv_cvt_float2_to_fp8x2(make_float2(c, d), __NV_SATFINITE, __NV_E4M3);
    return (uint32_t)lo | ((uint32_t)hi << 16);
}

__device__ __forceinline__ float2 bf2f2(uint32_t u) {
    return __bfloat1622float2(*reinterpret_cast<__nv_bfloat162*>(&u));
}

__global__ __launch_bounds__(256, 4) void din_main(
    const int* __restrict__ uh,
    const float* __restrict__ aw2)
{
    extern __shared__ char smraw[];
    Smem1& sm = *reinterpret_cast<Smem1*>(smraw);
    const int tid = threadIdx.x;
    const int b = blockIdx.x;
    const int warp = tid >> 5, lane = tid & 31;
    const int lr = lane >> 2, lc = lane & 3;
    uint32_t* PoolU = reinterpret_cast<uint32_t*>(sm.pool);

    // ---- stage indices, t, cb, w2; zero pads ----
    if (tid < 200) sm.idx[tid] = uh[b * SEQ + tid];
    if (tid >= 192) sm.t[tid - 192] = g_x[b * 128 + 64 + (tid - 192)];
    sm.cb[tid] = g_cb[b * 256 + tid];
    sm.w2[tid] = aw2[tid];
    if (tid < 160) reinterpret_cast<uint32_t*>(sm.A + 200 * 80)[tid] = 0u;  // pad rows 200..207
    __syncthreads();

    // ---- gather h (bf16 table): 1600 uint4 groups, front-batched ----
    {
        const uint4* ue = reinterpret_cast<const uint4*>(g_emb);   // 8 uint4 per row
        uint4 v[7];
        #pragma unroll
        for (int it = 0; it < 7; it++) {
            int i = tid + it * 256;
            if (i < 1600) v[it] = ue[(long)sm.idx[i >> 3] * 8 + (i & 7)];
        }
        #pragma unroll
        for (int it = 0; it < 7; it++) {
            int i = tid + it * 256;
            if (i < 1600) {
                int row = i >> 3, q = i & 7;
                uint4 vv = v[it];
                *reinterpret_cast<uint4*>(PoolU + row * 32 + q * 4) = vv;   // bf16 pool copy
                float2 f0 = bf2f2(vv.x), f1 = bf2f2(vv.y);
                float2 f2 = bf2f2(vv.z), f3 = bf2f2(vv.w);
                uint2 E;
                E.x = pack_e4m3_4(f0.x * FP8_SCALE, f0.y * FP8_SCALE,
                                  f1.x * FP8_SCALE, f1.y * FP8_SCALE);
                E.y = pack_e4m3_4(f2.x * FP8_SCALE, f2.y * FP8_SCALE,
                                  f3.x * FP8_SCALE, f3.y * FP8_SCALE);
                *reinterpret_cast<uint2*>(sm.A + row * 80 + q * 8) = E;
            }
        }
    }

    // ---- build fp8 B fragments, depth-1 pipelined over n-tiles ----
    uint32_t Breg[4][2][2];   // [ntile][ks2][part]
    {
        const uint4* W0q = reinterpret_cast<const uint4*>(g_W0f);
        const uint4* W1q = reinterpret_cast<const uint4*>(g_W1f);
        uint4 q[2][4];
        {
            int nb = (warp * 4 + 0) * 8 + lr;
            int base = nb * 8 + lc * 2;
            q[0][0] = W0q[base]; q[0][1] = W0q[base + 1];
            q[0][2] = W1q[base]; q[0][3] = W1q[base + 1];
        }
        #pragma unroll
        for (int nt = 0; nt < 4; nt++) {
            if (nt < 3) {
                int nb = (warp * 4 + nt + 1) * 8 + lr;
                int base = nb * 8 + lc * 2;
                q[(nt + 1) & 1][0] = W0q[base]; q[(nt + 1) & 1][1] = W0q[base + 1];
                q[(nt + 1) & 1][2] = W1q[base]; q[(nt + 1) & 1][3] = W1q[base + 1];
            }
            uint4 q0a = q[nt & 1][0], q0b = q[nt & 1][1];
            uint4 q1a = q[nt & 1][2], q1b = q[nt & 1][3];
            #pragma unroll
            for (int half = 0; half < 4; half++) {
                uint32_t w0lo = half == 0 ? q0a.x : half == 1 ? q0a.z : half == 2 ? q0b.x : q0b.z;
                uint32_t w0hi = half == 0 ? q0a.y : half == 1 ? q0a.w : half == 2 ? q0b.y : q0b.w;
                uint32_t w1lo = half == 0 ? q1a.x : half == 1 ? q1a.z : half == 2 ? q1b.x : q1b.z;
                uint32_t w1hi = half == 0 ? q1a.y : half == 1 ? q1a.w : half == 2 ? q1b.y : q1b.w;
                int k0 = (half >> 1) * 32 + (half & 1) * 16 + lc * 4;
                float2 x0 = bf2f2(w0lo), x1 = bf2f2(w0hi);
                float2 y0 = bf2f2(w1lo), y1 = bf2f2(w1hi);
                float f0 = fmaf(sm.t[k0 + 0], y0.x, x0.x) * FP8_SCALE;
                float f1 = fmaf(sm.t[k0 + 1], y0.y, x0.y) * FP8_SCALE;
                float f2 = fmaf(sm.t[k0 + 2], y1.x, x1.x) * FP8_SCALE;
                float f3 = fmaf(sm.t[k0 + 3], y1.y, x1.y) * FP8_SCALE;
                Breg[nt][half >> 1][half & 1] = pack_e4m3_4(f0, f1, f2, f3);
            }
        }
    }
    __syncthreads();

    // ---- packed epilogue constants: cb*4096 and w2 as half2 pairs ----
    __half2 cbp[4], w2p[4];
    const __half2 z2 = __floats2half2_rn(0.f, 0.f);
    #pragma unroll
    for (int nt = 0; nt < 4; nt++) {
        int n0 = (warp * 4 + nt) * 8 + lc * 2;
        cbp[nt] = __floats2half2_rn(sm.cb[n0] * 4096.f, sm.cb[n0 + 1] * 4096.f);
        w2p[nt] = __floats2half2_rn(sm.w2[n0], sm.w2[n0 + 1]);
    }

    const uint32_t abase = (uint32_t)__cvta_generic_to_shared(sm.A);
    const uint32_t rowsel = (lane & 15);
    const uint32_t khalf  = (lane & 16) ? 16u : 0u;

    // ---- GEMM: 13 slabs x 4 n-tiles, f16 accumulators, packed epilogue ----
    #pragma unroll 1
    for (int slab = 0; slab < 13; slab++) {
        int r0 = slab * 16 + lr;
        uint32_t lmbase = abase + (slab * 16 + rowsel) * 80 + khalf;
        uint32_t a[2][4];
        #pragma unroll
        for (int ks2 = 0; ks2 < 2; ks2++) {
            asm volatile(
                "ldmatrix.sync.aligned.m8n8.x4.shared.b16 {%0,%1,%2,%3}, [%4];\n"
                : "=r"(a[ks2][0]), "=r"(a[ks2][1]), "=r"(a[ks2][2]), "=r"(a[ks2][3])
                : "r"(lmbase + ks2 * 32));
        }
        uint32_t d[4][2];
        #pragma unroll
        for (int nt = 0; nt < 4; nt++) d[nt][0] = d[nt][1] = 0u;
        #pragma unroll
        for (int ks2 = 0; ks2 < 2; ks2++) {
            #pragma unroll
            for (int nt = 0; nt < 4; nt++)
                mma_fp8_h(d[nt][0], d[nt][1],
                          a[ks2][0], a[ks2][1], a[ks2][2], a[ks2][3],
                          Breg[nt][ks2][0], Breg[nt][ks2][1]);
        }
        __half2 l0 = z2, l1 = z2;
        #pragma unroll
        for (int nt = 0; nt < 4; nt++) {
            __half2 d0 = *reinterpret_cast<__half2*>(&d[nt][0]);
            __half2 d1 = *reinterpret_cast<__half2*>(&d[nt][1]);
            l0 = __hfma2(__hmax2(__hadd2(d0, cbp[nt]), z2), w2p[nt], l0);
            l1 = __hfma2(__hmax2(__hadd2(d1, cbp[nt]), z2), w2p[nt], l1);
        }
        // pack (row r0, row r0+8) partial logits into one half2, shfl-reduce over lc
        __half2 lp = __halves2half2(__hadd(__low2half(l0), __high2half(l0)),
                                    __hadd(__low2half(l1), __high2half(l1)));
        uint32_t lpu = *reinterpret_cast<uint32_t*>(&lp);
        #pragma unroll
        for (int o = 1; o <= 2; o <<= 1) {
            uint32_t other = __shfl_xor_sync(0xffffffffu, lpu, o);
            __half2 s = __hadd2(*reinterpret_cast<__half2*>(&lpu),
                                *reinterpret_cast<__half2*>(&other));
            lpu = *reinterpret_cast<uint32_t*>(&s);
        }
        if (lc == 0) {
            __half2 s = *reinterpret_cast<__half2*>(&lpu);
            sm.plog[warp][r0]     = __low2float(s) * INV_SCALE;
            sm.plog[warp][r0 + 8] = __high2float(s) * INV_SCALE;
        }
    }
    __syncthreads();

    // ---- softmax over 200 logits (sum 8 warp-partials; no max-sub: |logit| << 1) ----
    {
        float v = 0.f;
        if (tid < SEQ) {
            #pragma unroll
            for (int w = 0; w < 8; w++) v += sm.plog[w][tid];
        }
        float ev = (tid < SEQ) ? __expf(v) : 0.f;
        float s = ev;
        #pragma unroll
        for (int o = 16; o > 0; o >>= 1) s += __shfl_xor_sync(0xffffffffu, s, o);
        if (lane == 0) sm.red[warp] = s;
        __syncthreads();
        if (tid == 0) {
            float ss = 0.f;
            #pragma unroll
            for (int w = 0; w < 8; w++) ss += sm.red[w];
            sm.red[8] = 1.f / ss;
        }
        __syncthreads();
        if (tid < SEQ) sm.logits[tid] = ev * sm.red[8];
    }
    __syncthreads();

    // ---- weighted pooling from bf16 pool tile (partials reuse plog space) ----
    float* part = &sm.plog[0][0];    // 8 chunks x 64 floats
    {
        int e2 = lane, chunk = warp;
        float acc0 = 0.f, acc1 = 0.f;
        int s0 = chunk * 25;
        #pragma unroll 5
        for (int s = s0; s < s0 + 25; s++) {
            float w = sm.logits[s];
            uint32_t u = PoolU[s * 32 + e2];
            __nv_bfloat162 h2 = *reinterpret_cast<__nv_bfloat162*>(&u);
            acc0 = fmaf(w, __bfloat162float(h2.x), acc0);
            acc1 = fmaf(w, __bfloat162float(h2.y), acc1);
        }
        part[chunk * 64 + e2 * 2]     = acc0;
        part[chunk * 64 + e2 * 2 + 1] = acc1;
    }
    __syncthreads();
    if (tid < 64) {
        float v = 0.f;
        #pragma unroll
        for (int c8 = 0; c8 < 8; c8++) v += part[c8 * 64 + tid];
        g_x[b * 128 + tid] = v;
    }
}

// ================= kernel 2: prediction head via PROVEN bf16/f32 mma (32 rows/block) =================
struct Smem3 {
    __nv_bfloat16 xh[32 * 136];   // x bf16, row stride 136 halves (272 B)
    float b1s[256];
    float w2s[256];
    float plog[8][32];            // per-warp partial z
};

__global__ __launch_bounds__(256, 1) void din_mlp(
    const float* __restrict__ mb1,
    const float* __restrict__ mw2, const float* __restrict__ mb2,
    float* __restrict__ out)
{
    extern __shared__ char smraw[];
    Smem3& sm = *reinterpret_cast<Smem3*>(smraw);
    const int tid = threadIdx.x;
    const int warp = tid >> 5, lane = tid & 31;
    const int lr = lane >> 2, lc = lane & 3;
    const int b0 = blockIdx.x * 32;

    // ---- stage x [32 x 128] fp32 -> bf16 (stride 136 halves) ----
    {
        const float4* gx4 = reinterpret_cast<const float4*>(g_x);
        #pragma unroll
        for (int it = 0; it < 4; it++) {
            int i = tid + it * 256;          // 0..1023 = 32 rows x 32 float4
            int row = i >> 5, q = i & 31;
            float4 v = gx4[(long)b0 * 32 + i];
            __nv_bfloat162 h0 = __floats2bfloat162_rn(v.x, v.y);
            __nv_bfloat162 h1 = __floats2bfloat162_rn(v.z, v.w);
            uint2 P;
            P.x = *reinterpret_cast<uint32_t*>(&h0);
            P.y = *reinterpret_cast<uint32_t*>(&h1);
            *reinterpret_cast<uint2*>(&sm.xh[row * 136 + q * 4]) = P;
        }
    }
    sm.b1s[tid] = mb1[tid];
    sm.w2s[tid] = mw2[tid];

    // ---- B fragments: warp's 4 n-tiles x 8 k-steps from g_mw1b [n][k] bf16 ----
    uint32_t Breg[4][8][2];
    {
        const uint32_t* Wg = reinterpret_cast<const uint32_t*>(g_mw1b);
        #pragma unroll
        for (int nt = 0; nt < 4; nt++) {
            int n = (warp * 4 + nt) * 8 + lr;
            #pragma unroll
            for (int ks = 0; ks < 8; ks++) {
                Breg[nt][ks][0] = Wg[n * 64 + ks * 8 + lc];
                Breg[nt][ks][1] = Wg[n * 64 + ks * 8 + lc + 4];
            }
        }
    }
    __syncthreads();

    // f32 epilogue constants
    float b1v[4][2], w2v[4][2];
    #pragma unroll
    for (int nt = 0; nt < 4; nt++) {
        int n0 = (warp * 4 + nt) * 8 + lc * 2;
        b1v[nt][0] = sm.b1s[n0];     b1v[nt][1] = sm.b1s[n0 + 1];
        w2v[nt][0] = sm.w2s[n0];     w2v[nt][1] = sm.w2s[n0 + 1];
    }

    const uint32_t abase = (uint32_t)__cvta_generic_to_shared(sm.xh);
    const uint32_t rowsel = (lane & 15);
    const uint32_t khalf  = (lane & 16) ? 16u : 0u;

    // ---- GEMM: 2 slabs x 4 n-tiles x 8 k-steps, f32 accumulate ----
    #pragma unroll 1
    for (int slab = 0; slab < 2; slab++) {
        int r0 = slab * 16 + lr;
        uint32_t lmbase = abase + (slab * 16 + rowsel) * 272 + khalf;
        uint32_t a[8][4];
        #pragma unroll
        for (int ks = 0; ks < 8; ks++) {
            asm volatile(
                "ldmatrix.sync.aligned.m8n8.x4.shared.b16 {%0,%1,%2,%3}, [%4];\n"
                : "=r"(a[ks][0]), "=r"(a[ks][1]), "=r"(a[ks][2]), "=r"(a[ks][3])
                : "r"(lmbase + ks * 32));
        }
        float lp0 = 0.f, lp1 = 0.f;
        #pragma unroll
        for (int nt = 0; nt < 4; nt++) {
            float c0 = 0.f, c1 = 0.f, c2 = 0.f, c3 = 0.f;
            #pragma unroll
            for (int ks = 0; ks < 8; ks++)
                mma16816(c0, c1, c2, c3,
                         a[ks][0], a[ks][1], a[ks][2], a[ks][3],
                         Breg[nt][ks][0], Breg[nt][ks][1]);
            lp0 += fmaxf(c0 + b1v[nt][0], 0.f) * w2v[nt][0]
                 + fmaxf(c1 + b1v[nt][1], 0.f) * w2v[nt][1];
            lp1 += fmaxf(c2 + b1v[nt][0], 0.f) * w2v[nt][0]
                 + fmaxf(c3 + b1v[nt][1], 0.f) * w2v[nt][1];
        }
        lp0 += __shfl_xor_sync(0xffffffffu, lp0, 1);
        lp0 += __shfl_xor_sync(0xffffffffu, lp0, 2);
        lp1 += __shfl_xor_sync(0xffffffffu, lp1, 1);
        lp1 += __shfl_xor_sync(0xffffffffu, lp1, 2);
        if (lc == 0) {
            sm.plog[warp][r0]     = lp0;
            sm.plog[warp][r0 + 8] = lp1;
        }
    }
    __syncthreads();

    if (tid < 32) {
        float z = mb2[0];
        #pragma unroll
        for (int w = 0; w < 8; w++) z += sm.plog[w][tid];
        out[b0 + tid] = 1.f / (1.f + __expf(-z));
    }
}

// ================= launch =================
extern "C" void kernel_launch(void* const* d_in, const int* in_sizes, int n_in,
                              void* d_out, int out_size) {
    const int*   uh   = (const int*)d_in[0];
    const int*   ti   = (const int*)d_in[1];
    const float* uemb = (const float*)d_in[2];
    const float* iemb = (const float*)d_in[3];
    const float* aw1  = (const float*)d_in[4];
    const float* ab1  = (const float*)d_in[5];
    const float* aw2  = (const float*)d_in[6];
    // d_in[7] attn_b2: softmax-invariant, unused
    const float* mw1  = (const float*)d_in[8];
    const float* mb1  = (const float*)d_in[9];
    const float* mw2  = (const float*)d_in[10];
    const float* mb2  = (const float*)d_in[11];
    float* out = (float*)d_out;

    cudaFuncSetAttribute(din_main, cudaFuncAttributeMaxDynamicSharedMemorySize, (int)sizeof(Smem1));
    cudaFuncSetAttribute(din_mlp,  cudaFuncAttributeMaxDynamicSharedMemorySize, (int)sizeof(Smem3));

    prep_conv<<<2048, 256>>>(uemb, aw1, mw1);
    prep_misc<<<512, 256>>>(aw1, ab1, ti, iemb);
    din_main<<<BATCH, 256, sizeof(Smem1)>>>(uh, aw2);
    din_mlp<<<128, 256, sizeof(Smem3)>>>(mb1, mw2, mb2, out);
}